// round 4
// baseline (speedup 1.0000x reference)
// NodeContrastiveLoss — fused int8 mma.sync (IMMA) GEMM + streaming log-sum-exp.
// R4: legacy-HMMA MAC-rate wall (686us insensitive to scheduling) -> switch to
// s8 IMMA m16n8k32 (2x MACs/instr, exact int accumulation), 148 persistent CTAs
// over linearized work units (was 128/148 SMs), global per-row exp-sum
// accumulation, pos-dot computed exactly in fp32 in the normalize kernel.
#include <cuda_runtime.h>
#include <cuda_bf16.h>
#include <cstdint>
#include <cstddef>

#define N_ROWS 16384
#define DIM    128
#define NSM    148
#define TOTAL_UNITS 32768   // 128 row-tiles * 256 b-tiles

#define INV_TAU 14.285714285714286f
#define K1F     20.609929155556620f    // log2(e)/tau
#define C1F     (K1F / 16129.0f)       // K1 / 127^2 (int-dot scale)
#define LN2F    0.6931471805599453f

static __device__ uint32_t g_q1[(size_t)N_ROWS * 32];   // int8 rows, packed 4/word
static __device__ uint32_t g_q2[(size_t)N_ROWS * 32];
static __device__ float    g_pos[N_ROWS];
static __device__ float    g_rowsum[N_ROWS];
static __device__ float    g_bsum[128];

// ---------------- helpers ----------------
__device__ __forceinline__ uint32_t smem_u32(const void* p) {
    uint32_t r;
    asm("{ .reg .u64 t; cvta.to.shared.u64 t, %1; cvt.u32.u64 %0, t; }" : "=r"(r) : "l"(p));
    return r;
}
__device__ __forceinline__ void cp_async16(uint32_t dst, const void* src) {
    asm volatile("cp.async.cg.shared.global [%0], [%1], 16;" :: "r"(dst), "l"(src) : "memory");
}
__device__ __forceinline__ void cp_commit() { asm volatile("cp.async.commit_group;" ::: "memory"); }
template <int N>
__device__ __forceinline__ void cp_wait() { asm volatile("cp.async.wait_group %0;" :: "n"(N) : "memory"); }

__device__ __forceinline__ void ldsm4(uint32_t r[4], uint32_t addr) {
    asm volatile("ldmatrix.sync.aligned.m8n8.x4.shared.b16 {%0,%1,%2,%3}, [%4];"
                 : "=r"(r[0]), "=r"(r[1]), "=r"(r[2]), "=r"(r[3]) : "r"(addr));
}
__device__ __forceinline__ void imma16832(int c[4], const uint32_t a[4], uint32_t b0, uint32_t b1) {
    asm volatile(
        "mma.sync.aligned.m16n8k32.row.col.s32.s8.s8.s32 "
        "{%0,%1,%2,%3}, {%4,%5,%6,%7}, {%8,%9}, {%0,%1,%2,%3};"
        : "+r"(c[0]), "+r"(c[1]), "+r"(c[2]), "+r"(c[3])
        : "r"(a[0]), "r"(a[1]), "r"(a[2]), "r"(a[3]), "r"(b0), "r"(b1));
}
__device__ __forceinline__ float ex2f(float x) { float y; asm("ex2.approx.f32 %0, %1;" : "=f"(y) : "f"(x)); return y; }
__device__ __forceinline__ float lg2f(float x) { float y; asm("lg2.approx.f32 %0, %1;" : "=f"(y) : "f"(x)); return y; }

// int8 tile in SMEM: 128 rows x 128 B (8 chunks of 16 B), XOR swizzle.
__device__ __forceinline__ uint32_t swz8(int row, int c) {
    return (uint32_t)(row * 128 + (((c ^ row) & 7) << 4) + ((c & ~7) << 4));
}

// ---------------- SMEM layout (dynamic, 48 KB) ----------------
#define SMEM_A  0
#define SMEM_B0 16384
#define SMEM_B1 32768
#define SMEM_TOTAL 49152

__device__ __forceinline__ const char* tile_src(int bt, int crow) {
    const uint32_t* q = (bt & 128) ? g_q1 : g_q2;
    return (const char*)q + ((size_t)((bt & 127) * 128 + crow) * 128);
}

// ---------------- kernel 1: normalize + quantize + exact pos ----------------
__device__ __forceinline__ float dot4(float4 a, float4 b) {
    return a.x * b.x + a.y * b.y + a.z * b.z + a.w * b.w;
}
__device__ __forceinline__ uint32_t pack4(float4 v, float s) {
    int q0 = __float2int_rn(v.x * s), q1 = __float2int_rn(v.y * s);
    int q2 = __float2int_rn(v.z * s), q3 = __float2int_rn(v.w * s);
    return (uint32_t)(q0 & 0xff) | ((uint32_t)(q1 & 0xff) << 8)
         | ((uint32_t)(q2 & 0xff) << 16) | ((uint32_t)q3 << 24);
}
__global__ void __launch_bounds__(256) norm_kernel(const float* __restrict__ z1,
                                                   const float* __restrict__ z2) {
    int gw = blockIdx.x * 8 + (threadIdx.x >> 5);
    int lane = threadIdx.x & 31;
    if (threadIdx.x < 8) g_rowsum[blockIdx.x * 8 + threadIdx.x] = 0.f;
    float4 v1 = ((const float4*)(z1 + (size_t)gw * DIM))[lane];
    float4 v2 = ((const float4*)(z2 + (size_t)gw * DIM))[lane];
    float s1 = dot4(v1, v1), s2 = dot4(v2, v2), s12 = dot4(v1, v2);
#pragma unroll
    for (int o = 16; o; o >>= 1) {
        s1  += __shfl_xor_sync(0xffffffffu, s1, o);
        s2  += __shfl_xor_sync(0xffffffffu, s2, o);
        s12 += __shfl_xor_sync(0xffffffffu, s12, o);
    }
    float i1 = rsqrtf(s1), i2 = rsqrtf(s2);
    if (lane == 0) g_pos[gw] = s12 * i1 * i2;   // exact fp32 positive similarity
    g_q1[(size_t)gw * 32 + lane] = pack4(v1, i1 * 127.0f);
    g_q2[(size_t)gw * 32 + lane] = pack4(v2, i2 * 127.0f);
}

// ---------------- epilogue for one nb block ----------------
// MODE: 0 plain, 2 = z1z1 diag tile (exact structural diag skip)
template <int MODE>
__device__ __forceinline__ void epi_i8(int nbase, const int clo[4], const int chi[4],
                                       int r0, int c0, float& racc0, float& racc1) {
#pragma unroll
    for (int i = 0; i < 4; i++) {
        const int jl = nbase + c0 + (i & 1);
        const int jh = jl + 8;
        const int rr = r0 + 8 * (i >> 1);
        float xl = __int2float_rn(clo[i]);
        float xh = __int2float_rn(chi[i]);
        float el = ex2f(fmaf(xl, C1F, -K1F));
        float eh = ex2f(fmaf(xh, C1F, -K1F));
        if (MODE == 2) {
            if (jl == rr) el = 0.f;
            if (jh == rr) eh = 0.f;
        }
        float e = el + eh;
        if (i >> 1) racc1 += e; else racc0 += e;
    }
}

// ---------------- tile consumer (int8) ----------------
template <int MODE>
__device__ __forceinline__ void consume_tile_i8(
    uint32_t sB, const uint32_t a[4][4], int brow, int bsel,
    int r0, int c0, float& racc0, float& racc1)
{
    const int rx = brow & 7;
#pragma unroll
    for (int nbp = 0; nbp < 4; nbp++) {
        const int nb0 = nbp * 2, nb1 = nb0 + 1;
        const uint32_t base0 = sB + (uint32_t)((nb0 * 16 + brow) * 128);
        const uint32_t base1 = sB + (uint32_t)((nb1 * 16 + brow) * 128);

        uint32_t b0[2][4], b1[2][4];
        ldsm4(b0[0], base0 + (uint32_t)((bsel ^ rx) << 4));
        ldsm4(b1[0], base1 + (uint32_t)((bsel ^ rx) << 4));

        int c00[4] = {0,0,0,0}, c01[4] = {0,0,0,0};
        int c10[4] = {0,0,0,0}, c11[4] = {0,0,0,0};

#pragma unroll
        for (int ks = 0; ks < 4; ks++) {
            const int cur = ks & 1, nxt = cur ^ 1;
            if (ks < 3) {
                const uint32_t co = (uint32_t)(((2 * (ks + 1) + bsel) ^ rx) << 4);
                ldsm4(b0[nxt], base0 + co);
                ldsm4(b1[nxt], base1 + co);
            }
            // n-lo block uses regs {0,2} (k-lo,k-hi); n-hi uses {1,3}
            imma16832(c00, a[ks], b0[cur][0], b0[cur][2]);
            imma16832(c01, a[ks], b0[cur][1], b0[cur][3]);
            imma16832(c10, a[ks], b1[cur][0], b1[cur][2]);
            imma16832(c11, a[ks], b1[cur][1], b1[cur][3]);
        }
        epi_i8<MODE>(nb0 * 16, c00, c01, r0, c0, racc0, racc1);
        epi_i8<MODE>(nb1 * 16, c10, c11, r0, c0, racc0, racc1);
    }
}

// ---------------- kernel 2: main fused loop (persistent, 148 CTAs) ----------------
__global__ void __launch_bounds__(256, 1) ncl_main_kernel() {
    extern __shared__ char smem[];
    const uint32_t sb = smem_u32(smem);
    const int tid = threadIdx.x;
    const int wid = tid >> 5;
    const int lane = tid & 31;
    const int bx = blockIdx.x;

    // copy slots: row = tid/2, 4 chunks starting at (tid&1)*4
    const int crow = tid >> 1;
    const int cc0 = (tid & 1) * 4;
    uint32_t dsto[4];
#pragma unroll
    for (int c = 0; c < 4; c++) dsto[c] = swz8(crow, cc0 + c);

    // fragment addressing
    const int brow = lane & 15;          // ldsm row within 16-row block
    const int bsel = lane >> 4;          // k-chunk select (lo/hi 16B of k32)
    const int arow = wid * 16 + (lane & 15);
    const int r0 = wid * 16 + (lane >> 2);
    const int c0 = (lane & 3) * 2;

    int u = (bx * TOTAL_UNITS) / NSM;
    const int u1 = ((bx + 1) * TOTAL_UNITS) / NSM;

    while (u < u1) {
        const int rt = u >> 8;
        int bt = u & 255;
        const int cnt = min(u1 - u, 256 - bt);

        // load A tile (z1q rows rt*128..) and first B tile
        {
            const char* srcA = (const char*)g_q1 + ((size_t)(rt * 128 + crow) * 128) + cc0 * 16;
            const char* srcB = tile_src(bt, crow) + cc0 * 16;
#pragma unroll
            for (int c = 0; c < 4; c++) {
                cp_async16(sb + SMEM_A + dsto[c], srcA + c * 16);
                cp_async16(sb + SMEM_B0 + dsto[c], srcB + c * 16);
            }
        }
        cp_commit(); cp_wait<0>();
        __syncthreads();

        uint32_t a[4][4];
#pragma unroll
        for (int ks = 0; ks < 4; ks++)
            ldsm4(a[ks], sb + SMEM_A + swz8(arow, 2 * ks + bsel));

        float racc0 = 0.f, racc1 = 0.f;
        for (int i = 0; i < cnt; i++, bt++) {
            if (i + 1 < cnt) {
                const char* src = tile_src(bt + 1, crow) + cc0 * 16;
                const uint32_t dst = sb + (((i + 1) & 1) ? SMEM_B1 : SMEM_B0);
#pragma unroll
                for (int c = 0; c < 4; c++) cp_async16(dst + dsto[c], src + c * 16);
                cp_commit(); cp_wait<1>();
            } else {
                cp_wait<0>();
            }
            __syncthreads();
            const uint32_t sB = sb + ((i & 1) ? SMEM_B1 : SMEM_B0);
            if (bt == rt + 128)
                consume_tile_i8<2>(sB, a, brow, bsel, r0, c0, racc0, racc1);
            else
                consume_tile_i8<0>(sB, a, brow, bsel, r0, c0, racc0, racc1);
            __syncthreads();
        }

        // flush row partial sums (quad holds disjoint col-eighths of same rows)
        racc0 += __shfl_xor_sync(0xffffffffu, racc0, 1);
        racc0 += __shfl_xor_sync(0xffffffffu, racc0, 2);
        racc1 += __shfl_xor_sync(0xffffffffu, racc1, 1);
        racc1 += __shfl_xor_sync(0xffffffffu, racc1, 2);
        if ((lane & 3) == 0) {
            atomicAdd(&g_rowsum[rt * 128 + r0], racc0);
            atomicAdd(&g_rowsum[rt * 128 + r0 + 8], racc1);
        }
        u += cnt;
    }
}

// ---------------- kernel 3: per-row loss + block reduce ----------------
__global__ void __launch_bounds__(128) finalize1_kernel() {
    int i = blockIdx.x * 128 + threadIdx.x;
    int wid = threadIdx.x >> 5, lane = threadIdx.x & 31;
    float l = (1.0f - g_pos[i]) * INV_TAU + lg2f(g_rowsum[i]) * LN2F;
#pragma unroll
    for (int o = 16; o; o >>= 1) l += __shfl_xor_sync(0xffffffffu, l, o);
    __shared__ float red[4];
    if (lane == 0) red[wid] = l;
    __syncthreads();
    if (threadIdx.x == 0) g_bsum[blockIdx.x] = red[0] + red[1] + red[2] + red[3];
}

__global__ void finalize2_kernel(float* out) {
    int lane = threadIdx.x;
    float s = g_bsum[lane] + g_bsum[lane + 32] + g_bsum[lane + 64] + g_bsum[lane + 96];
#pragma unroll
    for (int o = 16; o; o >>= 1) s += __shfl_xor_sync(0xffffffffu, s, o);
    if (lane == 0) out[0] = s * (1.0f / (float)N_ROWS);
}

// ---------------- launch ----------------
extern "C" void kernel_launch(void* const* d_in, const int* in_sizes, int n_in,
                              void* d_out, int out_size) {
    const float* z1 = (const float*)d_in[0];
    const float* z2 = (const float*)d_in[1];
    float* out = (float*)d_out;
    (void)in_sizes; (void)n_in; (void)out_size;

    cudaFuncSetAttribute(ncl_main_kernel, cudaFuncAttributeMaxDynamicSharedMemorySize, SMEM_TOTAL);

    norm_kernel<<<N_ROWS / 8, 256>>>(z1, z2);
    ncl_main_kernel<<<NSM, 256, SMEM_TOTAL>>>();
    finalize1_kernel<<<128, 128>>>();
    finalize2_kernel<<<1, 32>>>(out);
}

// round 6
// speedup vs baseline: 1.7947x; 1.7947x over previous
// NodeContrastiveLoss — fused f16 mma.sync (f16 accumulator) + streaming LSE.
// R6: fix R5's swizzle bug (bit-3 of chunk index double-counted -> smem overrun
// -> illegal address). Reverted to the R3-proven XOR swizzle. Tests whether the
// legacy f16xf16->f16acc HMMA path runs 2x the f32-acc rate; keeps 148
// persistent CTAs + exact fp32 pos + structural diagonal skip.
#include <cuda_runtime.h>
#include <cuda_fp16.h>
#include <cstdint>
#include <cstddef>

#define N_ROWS 16384
#define DIM    128
#define NSM    148
#define TOTAL_UNITS 32768   // 128 row-tiles * 256 b-tiles (bt 0..127 = z2, 128..255 = z1)

#define INV_TAU 14.285714285714286f
#define K1F     20.609929155556620f    // log2(e)/tau
#define LN2F    0.6931471805599453f

static __device__ __half g_h1[(size_t)N_ROWS * DIM];
static __device__ __half g_h2[(size_t)N_ROWS * DIM];
static __device__ float  g_pos[N_ROWS];
static __device__ float  g_rowsum[N_ROWS];
static __device__ float  g_bsum[128];

// ---------------- helpers ----------------
__device__ __forceinline__ uint32_t smem_u32(const void* p) {
    uint32_t r;
    asm("{ .reg .u64 t; cvta.to.shared.u64 t, %1; cvt.u32.u64 %0, t; }" : "=r"(r) : "l"(p));
    return r;
}
__device__ __forceinline__ void cp_async16(uint32_t dst, const void* src) {
    asm volatile("cp.async.cg.shared.global [%0], [%1], 16;" :: "r"(dst), "l"(src) : "memory");
}
__device__ __forceinline__ void cp_commit() { asm volatile("cp.async.commit_group;" ::: "memory"); }
template <int N>
__device__ __forceinline__ void cp_wait() { asm volatile("cp.async.wait_group %0;" :: "n"(N) : "memory"); }

__device__ __forceinline__ void ldsm4(uint32_t r[4], uint32_t addr) {
    asm volatile("ldmatrix.sync.aligned.m8n8.x4.shared.b16 {%0,%1,%2,%3}, [%4];"
                 : "=r"(r[0]), "=r"(r[1]), "=r"(r[2]), "=r"(r[3]) : "r"(addr));
}
// f16 accumulator variant: D,C are 2 b32 regs (4 packed halves)
__device__ __forceinline__ void mma16816h(uint32_t c[2], const uint32_t a[4], uint32_t b0, uint32_t b1) {
    asm volatile(
        "mma.sync.aligned.m16n8k16.row.col.f16.f16.f16.f16 "
        "{%0,%1}, {%2,%3,%4,%5}, {%6,%7}, {%0,%1};"
        : "+r"(c[0]), "+r"(c[1])
        : "r"(a[0]), "r"(a[1]), "r"(a[2]), "r"(a[3]), "r"(b0), "r"(b1));
}
__device__ __forceinline__ float ex2f(float x) { float y; asm("ex2.approx.f32 %0, %1;" : "=f"(y) : "f"(x)); return y; }
__device__ __forceinline__ float lg2f(float x) { float y; asm("lg2.approx.f32 %0, %1;" : "=f"(y) : "f"(x)); return y; }

// f16 tile: 128 rows x 256 B (16 chunks of 16 B). XOR with 3-bit row key
// preserves bit 3 of the chunk index -> stays in-row (R3-proven form).
__device__ __forceinline__ uint32_t swz(int row, int c) {
    return (uint32_t)(row * 256 + ((c ^ (row & 7)) << 4));
}

// ---------------- SMEM layout (dynamic, 96 KB) ----------------
#define SMEM_A  0
#define SMEM_B0 32768
#define SMEM_B1 65536
#define SMEM_TOTAL 98304

__device__ __forceinline__ const char* tile_src(int bt, int crow) {
    const __half* h = (bt & 128) ? g_h1 : g_h2;
    return (const char*)h + ((size_t)((bt & 127) * 128 + crow) * 128) * 2;
}

// ---------------- kernel 1: normalize + f16 + exact pos ----------------
__device__ __forceinline__ float dot4(float4 a, float4 b) {
    return a.x * b.x + a.y * b.y + a.z * b.z + a.w * b.w;
}
__global__ void __launch_bounds__(256) norm_kernel(const float* __restrict__ z1,
                                                   const float* __restrict__ z2) {
    int gw = blockIdx.x * 8 + (threadIdx.x >> 5);
    int lane = threadIdx.x & 31;
    if (threadIdx.x < 8) g_rowsum[blockIdx.x * 8 + threadIdx.x] = 0.f;
    float4 v1 = ((const float4*)(z1 + (size_t)gw * DIM))[lane];
    float4 v2 = ((const float4*)(z2 + (size_t)gw * DIM))[lane];
    float s1 = dot4(v1, v1), s2 = dot4(v2, v2), s12 = dot4(v1, v2);
#pragma unroll
    for (int o = 16; o; o >>= 1) {
        s1  += __shfl_xor_sync(0xffffffffu, s1, o);
        s2  += __shfl_xor_sync(0xffffffffu, s2, o);
        s12 += __shfl_xor_sync(0xffffffffu, s12, o);
    }
    float i1 = rsqrtf(s1), i2 = rsqrtf(s2);
    if (lane == 0) g_pos[gw] = s12 * i1 * i2;   // exact fp32 positive similarity
    __half2* d1 = (__half2*)(g_h1 + (size_t)gw * DIM + lane * 4);
    __half2* d2 = (__half2*)(g_h2 + (size_t)gw * DIM + lane * 4);
    d1[0] = __floats2half2_rn(v1.x * i1, v1.y * i1);
    d1[1] = __floats2half2_rn(v1.z * i1, v1.w * i1);
    d2[0] = __floats2half2_rn(v2.x * i2, v2.y * i2);
    d2[1] = __floats2half2_rn(v2.z * i2, v2.w * i2);
}

// ---------------- epilogue for one 8-col mma result ----------------
// MODE: 0 plain, 2 = z1z1 diag tile (exact structural diag skip)
template <int MODE>
__device__ __forceinline__ void epi_h(int colb, const uint32_t c[2],
                                      int r0, int c0, float& racc0, float& racc1) {
    const int j0 = colb + c0, j1 = j0 + 1;
    float2 lo = __half22float2(*(const __half2*)&c[0]);  // row r0,   cols j0,j1
    float2 hi = __half22float2(*(const __half2*)&c[1]);  // row r0+8, cols j0,j1
    float e00 = ex2f(fmaf(lo.x, K1F, -K1F));
    float e01 = ex2f(fmaf(lo.y, K1F, -K1F));
    float e10 = ex2f(fmaf(hi.x, K1F, -K1F));
    float e11 = ex2f(fmaf(hi.y, K1F, -K1F));
    if (MODE == 2) {
        if (j0 == r0)     e00 = 0.f;
        if (j1 == r0)     e01 = 0.f;
        if (j0 == r0 + 8) e10 = 0.f;
        if (j1 == r0 + 8) e11 = 0.f;
    }
    racc0 += e00 + e01;
    racc1 += e10 + e11;
}

// ---------------- tile consumer ----------------
template <int MODE>
__device__ __forceinline__ void consume_tile_h(
    uint32_t sB, const uint32_t a[8][4], int brow_off, int bch,
    int r0, int c0, float& racc0, float& racc1)
{
    const int rx = brow_off & 7;
#pragma unroll
    for (int nbp = 0; nbp < 4; nbp++) {
        const int nb0 = nbp * 2, nb1 = nb0 + 1;
        const uint32_t base0 = sB + (uint32_t)((nb0 * 16 + brow_off) * 256);
        const uint32_t base1 = sB + (uint32_t)((nb1 * 16 + brow_off) * 256);

        uint32_t b0[2][4], b1[2][4];
        ldsm4(b0[0], base0 + (uint32_t)((bch ^ rx) << 4));
        ldsm4(b1[0], base1 + (uint32_t)((bch ^ rx) << 4));

        uint32_t c00[2] = {0u, 0u}, c01[2] = {0u, 0u};
        uint32_t c10[2] = {0u, 0u}, c11[2] = {0u, 0u};

#pragma unroll
        for (int ks = 0; ks < 8; ks++) {
            const int cur = ks & 1, nxt = cur ^ 1;
            if (ks < 7) {
                const uint32_t co = (uint32_t)((((ks + 1) * 2 + bch) ^ rx) << 4);
                ldsm4(b0[nxt], base0 + co);
                ldsm4(b1[nxt], base1 + co);
            }
            mma16816h(c00, a[ks], b0[cur][0], b0[cur][1]);
            mma16816h(c01, a[ks], b0[cur][2], b0[cur][3]);
            mma16816h(c10, a[ks], b1[cur][0], b1[cur][1]);
            mma16816h(c11, a[ks], b1[cur][2], b1[cur][3]);
        }
        epi_h<MODE>(nb0 * 16,     c00, r0, c0, racc0, racc1);
        epi_h<MODE>(nb0 * 16 + 8, c01, r0, c0, racc0, racc1);
        epi_h<MODE>(nb1 * 16,     c10, r0, c0, racc0, racc1);
        epi_h<MODE>(nb1 * 16 + 8, c11, r0, c0, racc0, racc1);
    }
}

// ---------------- kernel 2: main fused loop (persistent, 148 CTAs) ----------------
__global__ void __launch_bounds__(256, 1) ncl_main_kernel() {
    extern __shared__ char smem[];
    const uint32_t sb = smem_u32(smem);
    const int tid = threadIdx.x;
    const int wid = tid >> 5;
    const int lane = tid & 31;
    const int bx = blockIdx.x;

    // copy slots: row = tid/2, 8 chunks of 16B starting at (tid&1)*8
    const int crow = tid >> 1;
    const int cb = (tid & 1) * 8;
    uint32_t dsto[8];
#pragma unroll
    for (int c = 0; c < 8; c++) dsto[c] = swz(crow, cb + c);

    // fragment addressing (same mapping validated in the 686us bf16 kernel)
    const int brow_off = (lane & 7) + ((lane & 16) >> 1);
    const int bch = (lane >> 3) & 1;
    const int arow = wid * 16 + (lane & 15);
    const int ach = lane >> 4;
    const int r0 = wid * 16 + (lane >> 2);
    const int c0 = (lane & 3) * 2;

    int u = (bx * TOTAL_UNITS) / NSM;
    const int u1 = ((bx + 1) * TOTAL_UNITS) / NSM;

    while (u < u1) {
        const int rt = u >> 8;
        int bt = u & 255;
        const int cnt = min(u1 - u, 256 - bt);

        // load A tile (z1 rows rt*128..) and first B tile of this segment
        {
            const char* srcA = (const char*)g_h1 + ((size_t)(rt * 128 + crow) * 128) * 2 + cb * 16;
            const char* srcB = tile_src(bt, crow) + cb * 16;
#pragma unroll
            for (int c = 0; c < 8; c++) {
                cp_async16(sb + SMEM_A + dsto[c], srcA + c * 16);
                cp_async16(sb + SMEM_B0 + dsto[c], srcB + c * 16);
            }
        }
        cp_commit(); cp_wait<0>();
        __syncthreads();

        uint32_t a[8][4];
#pragma unroll
        for (int ks = 0; ks < 8; ks++)
            ldsm4(a[ks], sb + SMEM_A + swz(arow, ks * 2 + ach));

        float racc0 = 0.f, racc1 = 0.f;
        for (int i = 0; i < cnt; i++, bt++) {
            if (i + 1 < cnt) {
                const char* src = tile_src(bt + 1, crow) + cb * 16;
                const uint32_t dst = sb + (((i + 1) & 1) ? SMEM_B1 : SMEM_B0);
#pragma unroll
                for (int c = 0; c < 8; c++) cp_async16(dst + dsto[c], src + c * 16);
                cp_commit(); cp_wait<1>();
            } else {
                cp_wait<0>();
            }
            __syncthreads();
            const uint32_t sB = sb + ((i & 1) ? SMEM_B1 : SMEM_B0);
            if (bt == rt + 128)
                consume_tile_h<2>(sB, a, brow_off, bch, r0, c0, racc0, racc1);
            else
                consume_tile_h<0>(sB, a, brow_off, bch, r0, c0, racc0, racc1);
            __syncthreads();
        }

        // flush row partial sums (quad holds disjoint col chunks of same rows)
        racc0 += __shfl_xor_sync(0xffffffffu, racc0, 1);
        racc0 += __shfl_xor_sync(0xffffffffu, racc0, 2);
        racc1 += __shfl_xor_sync(0xffffffffu, racc1, 1);
        racc1 += __shfl_xor_sync(0xffffffffu, racc1, 2);
        if ((lane & 3) == 0) {
            atomicAdd(&g_rowsum[rt * 128 + r0], racc0);
            atomicAdd(&g_rowsum[rt * 128 + r0 + 8], racc1);
        }
        u += cnt;
    }
}

// ---------------- kernel 3: per-row loss + reductions ----------------
__global__ void __launch_bounds__(128) finalize1_kernel() {
    int i = blockIdx.x * 128 + threadIdx.x;
    int wid = threadIdx.x >> 5, lane = threadIdx.x & 31;
    float l = (1.0f - g_pos[i]) * INV_TAU + lg2f(g_rowsum[i]) * LN2F;
#pragma unroll
    for (int o = 16; o; o >>= 1) l += __shfl_xor_sync(0xffffffffu, l, o);
    __shared__ float red[4];
    if (lane == 0) red[wid] = l;
    __syncthreads();
    if (threadIdx.x == 0) g_bsum[blockIdx.x] = red[0] + red[1] + red[2] + red[3];
}

__global__ void finalize2_kernel(float* out) {
    int lane = threadIdx.x;
    float s = g_bsum[lane] + g_bsum[lane + 32] + g_bsum[lane + 64] + g_bsum[lane + 96];
#pragma unroll
    for (int o = 16; o; o >>= 1) s += __shfl_xor_sync(0xffffffffu, s, o);
    if (lane == 0) out[0] = s * (1.0f / (float)N_ROWS);
}

// ---------------- launch ----------------
extern "C" void kernel_launch(void* const* d_in, const int* in_sizes, int n_in,
                              void* d_out, int out_size) {
    const float* z1 = (const float*)d_in[0];
    const float* z2 = (const float*)d_in[1];
    float* out = (float*)d_out;
    (void)in_sizes; (void)n_in; (void)out_size;

    cudaFuncSetAttribute(ncl_main_kernel, cudaFuncAttributeMaxDynamicSharedMemorySize, SMEM_TOTAL);

    norm_kernel<<<N_ROWS / 8, 256>>>(z1, z2);
    ncl_main_kernel<<<NSM, 256, SMEM_TOTAL>>>();
    finalize1_kernel<<<128, 128>>>();
    finalize2_kernel<<<1, 32>>>(out);
}

// round 7
// speedup vs baseline: 1.9284x; 1.0745x over previous
// NodeContrastiveLoss — fused f16 HMMA + streaming LSE, z1z1 symmetry exploited.
// R7: legacy HMMA rate calibrated at 512 MAC/cyc/SM (f16acc == f32acc); the
// remaining lever is algorithmic: compute only the upper triangle of z1*z1^T
// (tile (rt,bt) feeds row-sums of rt AND col-sums -> rows of bt). 24640 units
// vs 32768 (-24.8% MACs) at ~4% epilogue overhead on triangle tiles.
#include <cuda_runtime.h>
#include <cuda_fp16.h>
#include <cstdint>
#include <cstddef>
#include <cmath>

#define N_ROWS 16384
#define DIM    128
#define NSM    148
#define UNITS_A 16384        // z1*z2^T: 128 rt x 128 bt
#define UNITS_TOTAL 24640    // + 8256 triangular z1*z1^T units

#define INV_TAU 14.285714285714286f
#define K1F     20.609929155556620f    // log2(e)/tau
#define LN2F    0.6931471805599453f

static __device__ __half g_h1[(size_t)N_ROWS * DIM];
static __device__ __half g_h2[(size_t)N_ROWS * DIM];
static __device__ float  g_pos[N_ROWS];
static __device__ float  g_rowsum[N_ROWS];
static __device__ float  g_bsum[128];

// ---------------- helpers ----------------
__device__ __forceinline__ uint32_t smem_u32(const void* p) {
    uint32_t r;
    asm("{ .reg .u64 t; cvta.to.shared.u64 t, %1; cvt.u32.u64 %0, t; }" : "=r"(r) : "l"(p));
    return r;
}
__device__ __forceinline__ void cp_async16(uint32_t dst, const void* src) {
    asm volatile("cp.async.cg.shared.global [%0], [%1], 16;" :: "r"(dst), "l"(src) : "memory");
}
__device__ __forceinline__ void cp_commit() { asm volatile("cp.async.commit_group;" ::: "memory"); }
template <int N>
__device__ __forceinline__ void cp_wait() { asm volatile("cp.async.wait_group %0;" :: "n"(N) : "memory"); }

__device__ __forceinline__ void ldsm4(uint32_t r[4], uint32_t addr) {
    asm volatile("ldmatrix.sync.aligned.m8n8.x4.shared.b16 {%0,%1,%2,%3}, [%4];"
                 : "=r"(r[0]), "=r"(r[1]), "=r"(r[2]), "=r"(r[3]) : "r"(addr));
}
__device__ __forceinline__ void mma16816h(uint32_t c[2], const uint32_t a[4], uint32_t b0, uint32_t b1) {
    asm volatile(
        "mma.sync.aligned.m16n8k16.row.col.f16.f16.f16.f16 "
        "{%0,%1}, {%2,%3,%4,%5}, {%6,%7}, {%0,%1};"
        : "+r"(c[0]), "+r"(c[1])
        : "r"(a[0]), "r"(a[1]), "r"(a[2]), "r"(a[3]), "r"(b0), "r"(b1));
}
__device__ __forceinline__ float ex2f(float x) { float y; asm("ex2.approx.f32 %0, %1;" : "=f"(y) : "f"(x)); return y; }
__device__ __forceinline__ float lg2f(float x) { float y; asm("lg2.approx.f32 %0, %1;" : "=f"(y) : "f"(x)); return y; }

// f16 tile: 128 rows x 256 B (16 chunks of 16 B). 3-bit XOR swizzle (in-row).
__device__ __forceinline__ uint32_t swz(int row, int c) {
    return (uint32_t)(row * 256 + ((c ^ (row & 7)) << 4));
}

// ---------------- SMEM layout (dynamic, 100 KB) ----------------
#define SMEM_A  0
#define SMEM_B0 32768
#define SMEM_B1 65536
#define SMEM_C  98304          // 8 warps x 128 floats col-sum staging (4 KB)
#define SMEM_TOTAL 102400

// ---------------- kernel 1: normalize + f16 + exact pos ----------------
__device__ __forceinline__ float dot4(float4 a, float4 b) {
    return a.x * b.x + a.y * b.y + a.z * b.z + a.w * b.w;
}
__global__ void __launch_bounds__(256) norm_kernel(const float* __restrict__ z1,
                                                   const float* __restrict__ z2) {
    int gw = blockIdx.x * 8 + (threadIdx.x >> 5);
    int lane = threadIdx.x & 31;
    if (threadIdx.x < 8) g_rowsum[blockIdx.x * 8 + threadIdx.x] = 0.f;
    float4 v1 = ((const float4*)(z1 + (size_t)gw * DIM))[lane];
    float4 v2 = ((const float4*)(z2 + (size_t)gw * DIM))[lane];
    float s1 = dot4(v1, v1), s2 = dot4(v2, v2), s12 = dot4(v1, v2);
#pragma unroll
    for (int o = 16; o; o >>= 1) {
        s1  += __shfl_xor_sync(0xffffffffu, s1, o);
        s2  += __shfl_xor_sync(0xffffffffu, s2, o);
        s12 += __shfl_xor_sync(0xffffffffu, s12, o);
    }
    float i1 = rsqrtf(s1), i2 = rsqrtf(s2);
    if (lane == 0) g_pos[gw] = s12 * i1 * i2;   // exact fp32 positive similarity
    __half2* d1 = (__half2*)(g_h1 + (size_t)gw * DIM + lane * 4);
    __half2* d2 = (__half2*)(g_h2 + (size_t)gw * DIM + lane * 4);
    d1[0] = __floats2half2_rn(v1.x * i1, v1.y * i1);
    d1[1] = __floats2half2_rn(v1.z * i1, v1.w * i1);
    d2[0] = __floats2half2_rn(v2.x * i2, v2.y * i2);
    d2[1] = __floats2half2_rn(v2.z * i2, v2.w * i2);
}

// ---------------- epilogue for one 8-col mma result ----------------
// MODE: 0 plain row sums; 2 diag tile (mask j==i, row sums);
//       3 triangle tile (row sums + col sums into cacc)
template <int MODE>
__device__ __forceinline__ void epi_h(int cbIdx, int sub, const uint32_t c[2],
                                      int r0, int c0, float& racc0, float& racc1,
                                      float cacc[16][2]) {
    const int colb = cbIdx * 8;
    const int j0 = colb + c0, j1 = j0 + 1;
    float2 lo = __half22float2(*(const __half2*)&c[0]);  // row r0,   cols j0,j1
    float2 hi = __half22float2(*(const __half2*)&c[1]);  // row r0+8, cols j0,j1
    float e00 = ex2f(fmaf(lo.x, K1F, -K1F));
    float e01 = ex2f(fmaf(lo.y, K1F, -K1F));
    float e10 = ex2f(fmaf(hi.x, K1F, -K1F));
    float e11 = ex2f(fmaf(hi.y, K1F, -K1F));
    if (MODE == 2) {
        if (j0 == r0)     e00 = 0.f;
        if (j1 == r0)     e01 = 0.f;
        if (j0 == r0 + 8) e10 = 0.f;
        if (j1 == r0 + 8) e11 = 0.f;
    }
    racc0 += e00 + e01;
    racc1 += e10 + e11;
    if (MODE == 3) {
        cacc[cbIdx][0] += e00 + e10;
        cacc[cbIdx][1] += e01 + e11;
    }
    (void)sub;
}

// ---------------- tile consumer ----------------
template <int MODE>
__device__ __forceinline__ void consume_tile_h(
    uint32_t sB, const uint32_t a[8][4], int brow_off, int bch,
    int r0, int c0, float& racc0, float& racc1, float cacc[16][2])
{
    const int rx = brow_off & 7;
#pragma unroll
    for (int nbp = 0; nbp < 4; nbp++) {
        const int nb0 = nbp * 2, nb1 = nb0 + 1;
        const uint32_t base0 = sB + (uint32_t)((nb0 * 16 + brow_off) * 256);
        const uint32_t base1 = sB + (uint32_t)((nb1 * 16 + brow_off) * 256);

        uint32_t b0[2][4], b1[2][4];
        ldsm4(b0[0], base0 + (uint32_t)((bch ^ rx) << 4));
        ldsm4(b1[0], base1 + (uint32_t)((bch ^ rx) << 4));

        uint32_t c00[2] = {0u, 0u}, c01[2] = {0u, 0u};
        uint32_t c10[2] = {0u, 0u}, c11[2] = {0u, 0u};

#pragma unroll
        for (int ks = 0; ks < 8; ks++) {
            const int cur = ks & 1, nxt = cur ^ 1;
            if (ks < 7) {
                const uint32_t co = (uint32_t)((((ks + 1) * 2 + bch) ^ rx) << 4);
                ldsm4(b0[nxt], base0 + co);
                ldsm4(b1[nxt], base1 + co);
            }
            mma16816h(c00, a[ks], b0[cur][0], b0[cur][1]);
            mma16816h(c01, a[ks], b0[cur][2], b0[cur][3]);
            mma16816h(c10, a[ks], b1[cur][0], b1[cur][1]);
            mma16816h(c11, a[ks], b1[cur][2], b1[cur][3]);
        }
        epi_h<MODE>(nb0 * 2,     0, c00, r0, c0, racc0, racc1, cacc);
        epi_h<MODE>(nb0 * 2 + 1, 0, c01, r0, c0, racc0, racc1, cacc);
        epi_h<MODE>(nb1 * 2,     0, c10, r0, c0, racc0, racc1, cacc);
        epi_h<MODE>(nb1 * 2 + 1, 0, c11, r0, c0, racc0, racc1, cacc);
    }
}

// triangular prefix: # tiles before row rt in phase B
__device__ __forceinline__ int triT(int rt) { return rt * 128 - (rt * (rt - 1)) / 2; }

// ---------------- kernel 2: main fused loop (persistent, 148 CTAs) ----------------
__global__ void __launch_bounds__(256, 1) ncl_main_kernel() {
    extern __shared__ char smem[];
    const uint32_t sb = smem_u32(smem);
    const int tid = threadIdx.x;
    const int wid = tid >> 5;
    const int lane = tid & 31;
    const int bx = blockIdx.x;

    const int crow = tid >> 1;
    const int cb = (tid & 1) * 8;
    uint32_t dsto[8];
#pragma unroll
    for (int c = 0; c < 8; c++) dsto[c] = swz(crow, cb + c);

    const int brow_off = (lane & 7) + ((lane & 16) >> 1);
    const int bch = (lane >> 3) & 1;
    const int arow = wid * 16 + (lane & 15);
    const int ach = lane >> 4;
    const int r0 = wid * 16 + (lane >> 2);
    const int c0 = (lane & 3) * 2;

    int u = (int)(((long long)bx * UNITS_TOTAL) / NSM);
    const int u1 = (int)(((long long)(bx + 1) * UNITS_TOTAL) / NSM);

    while (u < u1) {
        // decode segment: (phaseB?, rt, bt0, cnt)
        int rt, bt, phaseB;
        if (u < UNITS_A) {
            phaseB = 0;
            rt = u >> 7;
            bt = u & 127;
        } else {
            phaseB = 1;
            const int v = u - UNITS_A;
            float d = 128.5f * 128.5f - 2.0f * (float)v;
            rt = (int)(128.5f - sqrtf(d));
            if (rt < 0) rt = 0;
            if (rt > 127) rt = 127;
            while (rt < 127 && triT(rt + 1) <= v) rt++;
            while (rt > 0 && triT(rt) > v) rt--;
            bt = rt + (v - triT(rt));
        }
        const int segEnd = phaseB ? (u + (128 - bt)) : ((u & ~127) + 128);
        const int cnt = min(u1, segEnd) - u;
        const char* bsrc = (const char*)(phaseB ? g_h1 : g_h2);

        // load A tile (z1 rows rt*128..) and first B tile of this segment
        {
            const char* srcA = (const char*)g_h1 + ((size_t)(rt * 128 + crow) * 128) * 2 + cb * 16;
            const char* srcB = bsrc + ((size_t)(bt * 128 + crow) * 128) * 2 + cb * 16;
#pragma unroll
            for (int c = 0; c < 8; c++) {
                cp_async16(sb + SMEM_A + dsto[c], srcA + c * 16);
                cp_async16(sb + SMEM_B0 + dsto[c], srcB + c * 16);
            }
        }
        cp_commit(); cp_wait<0>();
        __syncthreads();

        uint32_t a[8][4];
#pragma unroll
        for (int ks = 0; ks < 8; ks++)
            ldsm4(a[ks], sb + SMEM_A + swz(arow, ks * 2 + ach));

        float racc0 = 0.f, racc1 = 0.f;
        for (int i = 0; i < cnt; i++, bt++) {
            if (i + 1 < cnt) {
                const char* src = bsrc + ((size_t)((bt + 1) * 128 + crow) * 128) * 2 + cb * 16;
                const uint32_t dst = sb + (((i + 1) & 1) ? SMEM_B1 : SMEM_B0);
#pragma unroll
                for (int c = 0; c < 8; c++) cp_async16(dst + dsto[c], src + c * 16);
                cp_commit(); cp_wait<1>();
            } else {
                cp_wait<0>();
            }
            __syncthreads();
            const uint32_t sB = sb + ((i & 1) ? SMEM_B1 : SMEM_B0);

            if (!phaseB) {
                consume_tile_h<0>(sB, a, brow_off, bch, r0, c0, racc0, racc1, nullptr);
            } else if (bt == rt) {
                consume_tile_h<2>(sB, a, brow_off, bch, r0, c0, racc0, racc1, nullptr);
            } else {
                float cacc[16][2];
#pragma unroll
                for (int k = 0; k < 16; k++) { cacc[k][0] = 0.f; cacc[k][1] = 0.f; }
                consume_tile_h<3>(sB, a, brow_off, bch, r0, c0, racc0, racc1, cacc);

                // ---- column-sum flush: rows of block bt get the transpose ----
#pragma unroll
                for (int k = 0; k < 16; k++) {
#pragma unroll
                    for (int q = 0; q < 2; q++) {
                        float vv = cacc[k][q];
                        vv += __shfl_xor_sync(0xffffffffu, vv, 4);
                        vv += __shfl_xor_sync(0xffffffffu, vv, 8);
                        vv += __shfl_xor_sync(0xffffffffu, vv, 16);
                        cacc[k][q] = vv;
                    }
                }
                if (lane < 4) {
                    float2* dst = (float2*)(smem + SMEM_C + wid * 512);
#pragma unroll
                    for (int k = 0; k < 16; k++)
                        dst[k * 4 + lane] = make_float2(cacc[k][0], cacc[k][1]);
                }
                __syncthreads();
                if (tid < 128) {
                    const float* sc = (const float*)(smem + SMEM_C);
                    float s = 0.f;
#pragma unroll
                    for (int w = 0; w < 8; w++) s += sc[w * 128 + tid];
                    atomicAdd(&g_rowsum[bt * 128 + tid], s);
                }
            }
            __syncthreads();
        }

        // flush row partial sums (quad holds disjoint col chunks of same rows)
        racc0 += __shfl_xor_sync(0xffffffffu, racc0, 1);
        racc0 += __shfl_xor_sync(0xffffffffu, racc0, 2);
        racc1 += __shfl_xor_sync(0xffffffffu, racc1, 1);
        racc1 += __shfl_xor_sync(0xffffffffu, racc1, 2);
        if ((lane & 3) == 0) {
            atomicAdd(&g_rowsum[rt * 128 + r0], racc0);
            atomicAdd(&g_rowsum[rt * 128 + r0 + 8], racc1);
        }
        u += cnt;
    }
}

// ---------------- kernel 3: per-row loss + reductions ----------------
__global__ void __launch_bounds__(128) finalize1_kernel() {
    int i = blockIdx.x * 128 + threadIdx.x;
    int wid = threadIdx.x >> 5, lane = threadIdx.x & 31;
    float l = (1.0f - g_pos[i]) * INV_TAU + lg2f(g_rowsum[i]) * LN2F;
#pragma unroll
    for (int o = 16; o; o >>= 1) l += __shfl_xor_sync(0xffffffffu, l, o);
    __shared__ float red[4];
    if (lane == 0) red[wid] = l;
    __syncthreads();
    if (threadIdx.x == 0) g_bsum[blockIdx.x] = red[0] + red[1] + red[2] + red[3];
}

__global__ void finalize2_kernel(float* out) {
    int lane = threadIdx.x;
    float s = g_bsum[lane] + g_bsum[lane + 32] + g_bsum[lane + 64] + g_bsum[lane + 96];
#pragma unroll
    for (int o = 16; o; o >>= 1) s += __shfl_xor_sync(0xffffffffu, s, o);
    if (lane == 0) out[0] = s * (1.0f / (float)N_ROWS);
}

// ---------------- launch ----------------
extern "C" void kernel_launch(void* const* d_in, const int* in_sizes, int n_in,
                              void* d_out, int out_size) {
    const float* z1 = (const float*)d_in[0];
    const float* z2 = (const float*)d_in[1];
    float* out = (float*)d_out;
    (void)in_sizes; (void)n_in; (void)out_size;

    cudaFuncSetAttribute(ncl_main_kernel, cudaFuncAttributeMaxDynamicSharedMemorySize, SMEM_TOTAL);

    norm_kernel<<<N_ROWS / 8, 256>>>(z1, z2);
    ncl_main_kernel<<<NSM, 256, SMEM_TOTAL>>>();
    finalize1_kernel<<<128, 128>>>();
    finalize2_kernel<<<1, 32>>>(out);
}

// round 8
// speedup vs baseline: 2.2469x; 1.1651x over previous
// NodeContrastiveLoss — fused f16 HMMA + streaming LSE, symmetric z1z1 triangle.
// R8: (1) balance phases separately across 148 CTAs (critical CTA was 100%
// expensive triangle tiles); (2) deferred double-buffered column flush (gather
// of tile i-1 overlaps tile i's MMA; mid-loop barrier removed); (3) 4-stage
// cp.async B pipeline + single __syncthreads per tile.
#include <cuda_runtime.h>
#include <cuda_fp16.h>
#include <cstdint>
#include <cstddef>
#include <cmath>

#define N_ROWS 16384
#define DIM    128
#define NSM    148
#define UNITS_A 16384        // z1*z2^T: 128 rt x 128 bt
#define UNITS_B 8256         // triangular z1*z1^T units (incl. diagonal)

#define INV_TAU 14.285714285714286f
#define K1F     20.609929155556620f    // log2(e)/tau
#define LN2F    0.6931471805599453f

static __device__ __half g_h1[(size_t)N_ROWS * DIM];
static __device__ __half g_h2[(size_t)N_ROWS * DIM];
static __device__ float  g_pos[N_ROWS];
static __device__ float  g_rowsum[N_ROWS];
static __device__ float  g_bsum[128];

// ---------------- helpers ----------------
__device__ __forceinline__ uint32_t smem_u32(const void* p) {
    uint32_t r;
    asm("{ .reg .u64 t; cvta.to.shared.u64 t, %1; cvt.u32.u64 %0, t; }" : "=r"(r) : "l"(p));
    return r;
}
__device__ __forceinline__ void cp_async16(uint32_t dst, const void* src) {
    asm volatile("cp.async.cg.shared.global [%0], [%1], 16;" :: "r"(dst), "l"(src) : "memory");
}
__device__ __forceinline__ void cp_commit() { asm volatile("cp.async.commit_group;" ::: "memory"); }
template <int N>
__device__ __forceinline__ void cp_wait() { asm volatile("cp.async.wait_group %0;" :: "n"(N) : "memory"); }
__device__ __forceinline__ void cp_wait_n(int n) {
    if (n >= 3) cp_wait<3>();
    else if (n == 2) cp_wait<2>();
    else if (n == 1) cp_wait<1>();
    else cp_wait<0>();
}

__device__ __forceinline__ void ldsm4(uint32_t r[4], uint32_t addr) {
    asm volatile("ldmatrix.sync.aligned.m8n8.x4.shared.b16 {%0,%1,%2,%3}, [%4];"
                 : "=r"(r[0]), "=r"(r[1]), "=r"(r[2]), "=r"(r[3]) : "r"(addr));
}
__device__ __forceinline__ void mma16816h(uint32_t c[2], const uint32_t a[4], uint32_t b0, uint32_t b1) {
    asm volatile(
        "mma.sync.aligned.m16n8k16.row.col.f16.f16.f16.f16 "
        "{%0,%1}, {%2,%3,%4,%5}, {%6,%7}, {%0,%1};"
        : "+r"(c[0]), "+r"(c[1])
        : "r"(a[0]), "r"(a[1]), "r"(a[2]), "r"(a[3]), "r"(b0), "r"(b1));
}
__device__ __forceinline__ float ex2f(float x) { float y; asm("ex2.approx.f32 %0, %1;" : "=f"(y) : "f"(x)); return y; }
__device__ __forceinline__ float lg2f(float x) { float y; asm("lg2.approx.f32 %0, %1;" : "=f"(y) : "f"(x)); return y; }

// f16 tile: 128 rows x 256 B (16 chunks of 16 B). 3-bit XOR swizzle (in-row).
__device__ __forceinline__ uint32_t swz(int row, int c) {
    return (uint32_t)(row * 256 + ((c ^ (row & 7)) << 4));
}

// ---------------- SMEM layout (dynamic, 168 KB) ----------------
#define SMEM_A  0
#define SMEM_B(s) (32768 + (s) * 32768)   // 4 stages
#define SMEM_C  163840                    // 2 x 4 KB col-sum staging
#define SMEM_TOTAL 172032

// ---------------- kernel 1: normalize + f16 + exact pos ----------------
__device__ __forceinline__ float dot4(float4 a, float4 b) {
    return a.x * b.x + a.y * b.y + a.z * b.z + a.w * b.w;
}
__global__ void __launch_bounds__(256) norm_kernel(const float* __restrict__ z1,
                                                   const float* __restrict__ z2) {
    int gw = blockIdx.x * 8 + (threadIdx.x >> 5);
    int lane = threadIdx.x & 31;
    if (threadIdx.x < 8) g_rowsum[blockIdx.x * 8 + threadIdx.x] = 0.f;
    float4 v1 = ((const float4*)(z1 + (size_t)gw * DIM))[lane];
    float4 v2 = ((const float4*)(z2 + (size_t)gw * DIM))[lane];
    float s1 = dot4(v1, v1), s2 = dot4(v2, v2), s12 = dot4(v1, v2);
#pragma unroll
    for (int o = 16; o; o >>= 1) {
        s1  += __shfl_xor_sync(0xffffffffu, s1, o);
        s2  += __shfl_xor_sync(0xffffffffu, s2, o);
        s12 += __shfl_xor_sync(0xffffffffu, s12, o);
    }
    float i1 = rsqrtf(s1), i2 = rsqrtf(s2);
    if (lane == 0) g_pos[gw] = s12 * i1 * i2;
    __half2* d1 = (__half2*)(g_h1 + (size_t)gw * DIM + lane * 4);
    __half2* d2 = (__half2*)(g_h2 + (size_t)gw * DIM + lane * 4);
    d1[0] = __floats2half2_rn(v1.x * i1, v1.y * i1);
    d1[1] = __floats2half2_rn(v1.z * i1, v1.w * i1);
    d2[0] = __floats2half2_rn(v2.x * i2, v2.y * i2);
    d2[1] = __floats2half2_rn(v2.z * i2, v2.w * i2);
}

// ---------------- epilogue ----------------
// MODE: 0 row sums; 2 diag tile (mask j==i); 3 triangle tile (row + col sums)
template <int MODE>
__device__ __forceinline__ void epi_h(int cbIdx, const uint32_t c[2],
                                      int r0, int c0, float& racc0, float& racc1,
                                      float cacc[16][2]) {
    const int colb = cbIdx * 8;
    const int j0 = colb + c0, j1 = j0 + 1;
    float2 lo = __half22float2(*(const __half2*)&c[0]);
    float2 hi = __half22float2(*(const __half2*)&c[1]);
    float e00 = ex2f(fmaf(lo.x, K1F, -K1F));
    float e01 = ex2f(fmaf(lo.y, K1F, -K1F));
    float e10 = ex2f(fmaf(hi.x, K1F, -K1F));
    float e11 = ex2f(fmaf(hi.y, K1F, -K1F));
    if (MODE == 2) {
        if (j0 == r0)     e00 = 0.f;
        if (j1 == r0)     e01 = 0.f;
        if (j0 == r0 + 8) e10 = 0.f;
        if (j1 == r0 + 8) e11 = 0.f;
    }
    racc0 += e00 + e01;
    racc1 += e10 + e11;
    if (MODE == 3) {
        cacc[cbIdx][0] += e00 + e10;
        cacc[cbIdx][1] += e01 + e11;
    }
}

// ---------------- tile consumer ----------------
template <int MODE>
__device__ __forceinline__ void consume_tile_h(
    uint32_t sB, const uint32_t a[8][4], int brow_off, int bch,
    int r0, int c0, float& racc0, float& racc1, float cacc[16][2])
{
    const int rx = brow_off & 7;
#pragma unroll
    for (int nbp = 0; nbp < 4; nbp++) {
        const int nb0 = nbp * 2, nb1 = nb0 + 1;
        const uint32_t base0 = sB + (uint32_t)((nb0 * 16 + brow_off) * 256);
        const uint32_t base1 = sB + (uint32_t)((nb1 * 16 + brow_off) * 256);

        uint32_t b0[2][4], b1[2][4];
        ldsm4(b0[0], base0 + (uint32_t)((bch ^ rx) << 4));
        ldsm4(b1[0], base1 + (uint32_t)((bch ^ rx) << 4));

        uint32_t c00[2] = {0u, 0u}, c01[2] = {0u, 0u};
        uint32_t c10[2] = {0u, 0u}, c11[2] = {0u, 0u};

#pragma unroll
        for (int ks = 0; ks < 8; ks++) {
            const int cur = ks & 1, nxt = cur ^ 1;
            if (ks < 7) {
                const uint32_t co = (uint32_t)((((ks + 1) * 2 + bch) ^ rx) << 4);
                ldsm4(b0[nxt], base0 + co);
                ldsm4(b1[nxt], base1 + co);
            }
            mma16816h(c00, a[ks], b0[cur][0], b0[cur][1]);
            mma16816h(c01, a[ks], b0[cur][2], b0[cur][3]);
            mma16816h(c10, a[ks], b1[cur][0], b1[cur][1]);
            mma16816h(c11, a[ks], b1[cur][2], b1[cur][3]);
        }
        epi_h<MODE>(nb0 * 2,     c00, r0, c0, racc0, racc1, cacc);
        epi_h<MODE>(nb0 * 2 + 1, c01, r0, c0, racc0, racc1, cacc);
        epi_h<MODE>(nb1 * 2,     c10, r0, c0, racc0, racc1, cacc);
        epi_h<MODE>(nb1 * 2 + 1, c11, r0, c0, racc0, racc1, cacc);
    }
}

__device__ __forceinline__ int triT(int rt) { return rt * 128 - (rt * (rt - 1)) / 2; }

// ---------------- kernel 2: main fused loop (persistent, 148 CTAs) ----------------
__global__ void __launch_bounds__(256, 1) ncl_main_kernel() {
    extern __shared__ char smem[];
    const uint32_t sb = smem_u32(smem);
    const int tid = threadIdx.x;
    const int wid = tid >> 5;
    const int lane = tid & 31;
    const int bx = blockIdx.x;

    const int crow = tid >> 1;
    const int cb = (tid & 1) * 8;
    uint32_t dsto[8];
#pragma unroll
    for (int c = 0; c < 8; c++) dsto[c] = swz(crow, cb + c);

    const int brow_off = (lane & 7) + ((lane & 16) >> 1);
    const int bch = (lane >> 3) & 1;
    const int arow = wid * 16 + (lane & 15);
    const int ach = lane >> 4;
    const int r0 = wid * 16 + (lane >> 2);
    const int c0 = (lane & 3) * 2;

#pragma unroll 1
    for (int phase = 0; phase < 2; phase++) {
        int u, u1;
        if (phase == 0) { u = (bx * UNITS_A) / NSM;  u1 = ((bx + 1) * UNITS_A) / NSM; }
        else            { u = (bx * UNITS_B) / NSM;  u1 = ((bx + 1) * UNITS_B) / NSM; }
        const char* bsrc = (const char*)(phase ? g_h1 : g_h2);

        while (u < u1) {
            int rt, bt;
            if (phase == 0) {
                rt = u >> 7;
                bt = u & 127;
            } else {
                float d = 128.5f * 128.5f - 2.0f * (float)u;
                rt = (int)(128.5f - sqrtf(d));
                if (rt < 0) rt = 0;
                if (rt > 127) rt = 127;
                while (rt < 127 && triT(rt + 1) <= u) rt++;
                while (rt > 0 && triT(rt) > u) rt--;
                bt = rt + (u - triT(rt));
            }
            const int cnt = min(u1 - u, 128 - bt);

            // group 0: A tile
            {
                const char* srcA = (const char*)g_h1 + ((size_t)(rt * 128 + crow) * 128) * 2 + cb * 16;
#pragma unroll
                for (int c = 0; c < 8; c++) cp_async16(sb + SMEM_A + dsto[c], srcA + c * 16);
                cp_commit();
            }
            // preload up to 3 B tiles, one group each
            const int npre = min(cnt, 3);
            for (int p = 0; p < npre; p++) {
                const char* src = bsrc + ((size_t)((bt + p) * 128 + crow) * 128) * 2 + cb * 16;
#pragma unroll
                for (int c = 0; c < 8; c++) cp_async16(sb + SMEM_B(p) + dsto[c], src + c * 16);
                cp_commit();
            }
            cp_wait_n(npre);   // A complete (pending <= npre B groups)
            __syncthreads();

            uint32_t a[8][4];
#pragma unroll
            for (int ks = 0; ks < 8; ks++)
                ldsm4(a[ks], sb + SMEM_A + swz(arow, ks * 2 + ach));

            float racc0 = 0.f, racc1 = 0.f;
            int pend_bt = -1, pend_slot = 0;

            for (int i = 0; i < cnt; i++) {
                const int btc = bt + i;
                cp_wait_n(min(3, cnt - 1 - i));   // tile i resident
                __syncthreads();                  // stage visible; prior consumes done

                // prefetch tile i+3 (stage reuse safe: all warps past tile i-1)
                if (i + 3 < cnt) {
                    const char* src = bsrc + ((size_t)((btc + 3) * 128 + crow) * 128) * 2 + cb * 16;
                    const uint32_t dst = sb + SMEM_B((i + 3) & 3);
#pragma unroll
                    for (int c = 0; c < 8; c++) cp_async16(dst + dsto[c], src + c * 16);
                    cp_commit();
                }

                // deferred gather of previous triangle tile's column sums
                if (pend_bt >= 0 && tid < 128) {
                    const float* sc = (const float*)(smem + SMEM_C + pend_slot * 4096);
                    float s = 0.f;
#pragma unroll
                    for (int w = 0; w < 8; w++) s += sc[w * 128 + tid];
                    atomicAdd(&g_rowsum[pend_bt * 128 + tid], s);
                }
                pend_bt = -1;

                const uint32_t sB = sb + SMEM_B(i & 3);
                if (phase == 0) {
                    consume_tile_h<0>(sB, a, brow_off, bch, r0, c0, racc0, racc1, nullptr);
                } else if (btc == rt) {
                    consume_tile_h<2>(sB, a, brow_off, bch, r0, c0, racc0, racc1, nullptr);
                } else {
                    float cacc[16][2];
#pragma unroll
                    for (int k = 0; k < 16; k++) { cacc[k][0] = 0.f; cacc[k][1] = 0.f; }
                    consume_tile_h<3>(sB, a, brow_off, bch, r0, c0, racc0, racc1, cacc);
#pragma unroll
                    for (int k = 0; k < 16; k++) {
#pragma unroll
                        for (int q = 0; q < 2; q++) {
                            float vv = cacc[k][q];
                            vv += __shfl_xor_sync(0xffffffffu, vv, 4);
                            vv += __shfl_xor_sync(0xffffffffu, vv, 8);
                            vv += __shfl_xor_sync(0xffffffffu, vv, 16);
                            cacc[k][q] = vv;
                        }
                    }
                    if (lane < 4) {
                        float2* dst = (float2*)(smem + SMEM_C + (i & 1) * 4096 + wid * 512);
#pragma unroll
                        for (int k = 0; k < 16; k++)
                            dst[k * 4 + lane] = make_float2(cacc[k][0], cacc[k][1]);
                    }
                    pend_bt = btc;
                    pend_slot = i & 1;
                }
            }

            __syncthreads();   // order last STS before drain
            if (pend_bt >= 0 && tid < 128) {
                const float* sc = (const float*)(smem + SMEM_C + pend_slot * 4096);
                float s = 0.f;
#pragma unroll
                for (int w = 0; w < 8; w++) s += sc[w * 128 + tid];
                atomicAdd(&g_rowsum[pend_bt * 128 + tid], s);
            }

            // flush row partial sums
            racc0 += __shfl_xor_sync(0xffffffffu, racc0, 1);
            racc0 += __shfl_xor_sync(0xffffffffu, racc0, 2);
            racc1 += __shfl_xor_sync(0xffffffffu, racc1, 1);
            racc1 += __shfl_xor_sync(0xffffffffu, racc1, 2);
            if ((lane & 3) == 0) {
                atomicAdd(&g_rowsum[rt * 128 + r0], racc0);
                atomicAdd(&g_rowsum[rt * 128 + r0 + 8], racc1);
            }
            u += cnt;
        }
    }
}

// ---------------- kernel 3: per-row loss + reductions ----------------
__global__ void __launch_bounds__(128) finalize1_kernel() {
    int i = blockIdx.x * 128 + threadIdx.x;
    int wid = threadIdx.x >> 5, lane = threadIdx.x & 31;
    float l = (1.0f - g_pos[i]) * INV_TAU + lg2f(g_rowsum[i]) * LN2F;
#pragma unroll
    for (int o = 16; o; o >>= 1) l += __shfl_xor_sync(0xffffffffu, l, o);
    __shared__ float red[4];
    if (lane == 0) red[wid] = l;
    __syncthreads();
    if (threadIdx.x == 0) g_bsum[blockIdx.x] = red[0] + red[1] + red[2] + red[3];
}

__global__ void finalize2_kernel(float* out) {
    int lane = threadIdx.x;
    float s = g_bsum[lane] + g_bsum[lane + 32] + g_bsum[lane + 64] + g_bsum[lane + 96];
#pragma unroll
    for (int o = 16; o; o >>= 1) s += __shfl_xor_sync(0xffffffffu, s, o);
    if (lane == 0) out[0] = s * (1.0f / (float)N_ROWS);
}

// ---------------- launch ----------------
extern "C" void kernel_launch(void* const* d_in, const int* in_sizes, int n_in,
                              void* d_out, int out_size) {
    const float* z1 = (const float*)d_in[0];
    const float* z2 = (const float*)d_in[1];
    float* out = (float*)d_out;
    (void)in_sizes; (void)n_in; (void)out_size;

    cudaFuncSetAttribute(ncl_main_kernel, cudaFuncAttributeMaxDynamicSharedMemorySize, SMEM_TOTAL);

    norm_kernel<<<N_ROWS / 8, 256>>>(z1, z2);
    ncl_main_kernel<<<NSM, 256, SMEM_TOTAL>>>();
    finalize1_kernel<<<128, 128>>>();
    finalize2_kernel<<<1, 32>>>(out);
}

// round 9
// speedup vs baseline: 2.2792x; 1.0144x over previous
// NodeContrastiveLoss — fused HMMA + streaming LSE, symmetric z1z1 triangle.
// R9: f32 mma accumulators (f16acc had no rate edge; kills 128 cvt/thread/tile)
// + 2-tile superstages (one __syncthreads + one cp.async group per 2 tiles)
// + 4-slot col-flush staging so the deferred gather stays race-free.
#include <cuda_runtime.h>
#include <cuda_fp16.h>
#include <cstdint>
#include <cstddef>
#include <cmath>

#define N_ROWS 16384
#define DIM    128
#define NSM    148
#define UNITS_A 16384        // z1*z2^T: 128 rt x 128 bt
#define UNITS_B 8256         // triangular z1*z1^T units (incl. diagonal)

#define INV_TAU 14.285714285714286f
#define K1F     20.609929155556620f    // log2(e)/tau
#define LN2F    0.6931471805599453f

static __device__ __half g_h1[(size_t)N_ROWS * DIM];
static __device__ __half g_h2[(size_t)N_ROWS * DIM];
static __device__ float  g_pos[N_ROWS];
static __device__ float  g_rowsum[N_ROWS];
static __device__ float  g_bsum[128];

// ---------------- helpers ----------------
__device__ __forceinline__ uint32_t smem_u32(const void* p) {
    uint32_t r;
    asm("{ .reg .u64 t; cvta.to.shared.u64 t, %1; cvt.u32.u64 %0, t; }" : "=r"(r) : "l"(p));
    return r;
}
__device__ __forceinline__ void cp_async16(uint32_t dst, const void* src) {
    asm volatile("cp.async.cg.shared.global [%0], [%1], 16;" :: "r"(dst), "l"(src) : "memory");
}
__device__ __forceinline__ void cp_commit() { asm volatile("cp.async.commit_group;" ::: "memory"); }
template <int N>
__device__ __forceinline__ void cp_wait() { asm volatile("cp.async.wait_group %0;" :: "n"(N) : "memory"); }

__device__ __forceinline__ void ldsm4(uint32_t r[4], uint32_t addr) {
    asm volatile("ldmatrix.sync.aligned.m8n8.x4.shared.b16 {%0,%1,%2,%3}, [%4];"
                 : "=r"(r[0]), "=r"(r[1]), "=r"(r[2]), "=r"(r[3]) : "r"(addr));
}
__device__ __forceinline__ void mma16816(float c[4], const uint32_t a[4], uint32_t b0, uint32_t b1) {
    asm volatile(
        "mma.sync.aligned.m16n8k16.row.col.f32.f16.f16.f32 "
        "{%0,%1,%2,%3}, {%4,%5,%6,%7}, {%8,%9}, {%0,%1,%2,%3};"
        : "+f"(c[0]), "+f"(c[1]), "+f"(c[2]), "+f"(c[3])
        : "r"(a[0]), "r"(a[1]), "r"(a[2]), "r"(a[3]), "r"(b0), "r"(b1));
}
__device__ __forceinline__ float ex2f(float x) { float y; asm("ex2.approx.f32 %0, %1;" : "=f"(y) : "f"(x)); return y; }
__device__ __forceinline__ float lg2f(float x) { float y; asm("lg2.approx.f32 %0, %1;" : "=f"(y) : "f"(x)); return y; }

// f16 tile: 128 rows x 256 B (16 chunks of 16 B). 3-bit XOR swizzle (in-row).
__device__ __forceinline__ uint32_t swz(int row, int c) {
    return (uint32_t)(row * 256 + ((c ^ (row & 7)) << 4));
}

// ---------------- SMEM layout (dynamic, 176 KB) ----------------
#define SMEM_A  0
#define SMEM_S(s) (32768 + (s) * 65536)   // 2 superstages x 64 KB (2 tiles each)
#define SMEM_C  163840                    // 4 x 4 KB col-sum staging slots
#define SMEM_TOTAL 180224

// ---------------- kernel 1: normalize + f16 + exact pos ----------------
__device__ __forceinline__ float dot4(float4 a, float4 b) {
    return a.x * b.x + a.y * b.y + a.z * b.z + a.w * b.w;
}
__global__ void __launch_bounds__(256) norm_kernel(const float* __restrict__ z1,
                                                   const float* __restrict__ z2) {
    int gw = blockIdx.x * 8 + (threadIdx.x >> 5);
    int lane = threadIdx.x & 31;
    if (threadIdx.x < 8) g_rowsum[blockIdx.x * 8 + threadIdx.x] = 0.f;
    float4 v1 = ((const float4*)(z1 + (size_t)gw * DIM))[lane];
    float4 v2 = ((const float4*)(z2 + (size_t)gw * DIM))[lane];
    float s1 = dot4(v1, v1), s2 = dot4(v2, v2), s12 = dot4(v1, v2);
#pragma unroll
    for (int o = 16; o; o >>= 1) {
        s1  += __shfl_xor_sync(0xffffffffu, s1, o);
        s2  += __shfl_xor_sync(0xffffffffu, s2, o);
        s12 += __shfl_xor_sync(0xffffffffu, s12, o);
    }
    float i1 = rsqrtf(s1), i2 = rsqrtf(s2);
    if (lane == 0) g_pos[gw] = s12 * i1 * i2;
    __half2* d1 = (__half2*)(g_h1 + (size_t)gw * DIM + lane * 4);
    __half2* d2 = (__half2*)(g_h2 + (size_t)gw * DIM + lane * 4);
    d1[0] = __floats2half2_rn(v1.x * i1, v1.y * i1);
    d1[1] = __floats2half2_rn(v1.z * i1, v1.w * i1);
    d2[0] = __floats2half2_rn(v2.x * i2, v2.y * i2);
    d2[1] = __floats2half2_rn(v2.z * i2, v2.w * i2);
}

// ---------------- epilogue for one nb block (f32 accumulators) ----------------
// MODE: 0 row sums; 2 diag tile (mask j==i); 3 triangle tile (row + col sums)
template <int MODE>
__device__ __forceinline__ void epi_f(int nb, const float clo[4], const float chi[4],
                                      int r0, int c0, float& racc0, float& racc1,
                                      float cacc[16][2]) {
    const int nbase = nb * 16;
#pragma unroll
    for (int i = 0; i < 4; i++) {
        const int jl = nbase + c0 + (i & 1);
        const int jh = jl + 8;
        const int rr = r0 + 8 * (i >> 1);
        float el = ex2f(fmaf(clo[i], K1F, -K1F));
        float eh = ex2f(fmaf(chi[i], K1F, -K1F));
        if (MODE == 2) {
            if (jl == rr) el = 0.f;
            if (jh == rr) eh = 0.f;
        }
        if (i >> 1) racc1 += el + eh; else racc0 += el + eh;
        if (MODE == 3) {
            cacc[nb * 2][i & 1]     += el;
            cacc[nb * 2 + 1][i & 1] += eh;
        }
    }
}

// ---------------- tile consumer (R3-validated fragment mapping) ----------------
template <int MODE>
__device__ __forceinline__ void consume_tile_f(
    uint32_t sB, const uint32_t a[8][4], int brow_off, int bch,
    int r0, int c0, float& racc0, float& racc1, float cacc[16][2])
{
    const int rx = brow_off & 7;
#pragma unroll
    for (int nbp = 0; nbp < 4; nbp++) {
        const int nb0 = nbp * 2, nb1 = nb0 + 1;
        const uint32_t base0 = sB + (uint32_t)((nb0 * 16 + brow_off) * 256);
        const uint32_t base1 = sB + (uint32_t)((nb1 * 16 + brow_off) * 256);

        uint32_t b0[2][4], b1[2][4];
        ldsm4(b0[0], base0 + (uint32_t)((bch ^ rx) << 4));
        ldsm4(b1[0], base1 + (uint32_t)((bch ^ rx) << 4));

        float c00[4] = {0.f, 0.f, 0.f, 0.f};
        float c01[4] = {0.f, 0.f, 0.f, 0.f};
        float c10[4] = {0.f, 0.f, 0.f, 0.f};
        float c11[4] = {0.f, 0.f, 0.f, 0.f};

#pragma unroll
        for (int ks = 0; ks < 8; ks++) {
            const int cur = ks & 1, nxt = cur ^ 1;
            if (ks < 7) {
                const uint32_t co = (uint32_t)((((ks + 1) * 2 + bch) ^ rx) << 4);
                ldsm4(b0[nxt], base0 + co);
                ldsm4(b1[nxt], base1 + co);
            }
            mma16816(c00, a[ks], b0[cur][0], b0[cur][1]);
            mma16816(c01, a[ks], b0[cur][2], b0[cur][3]);
            mma16816(c10, a[ks], b1[cur][0], b1[cur][1]);
            mma16816(c11, a[ks], b1[cur][2], b1[cur][3]);
        }
        epi_f<MODE>(nb0, c00, c01, r0, c0, racc0, racc1, cacc);
        epi_f<MODE>(nb1, c10, c11, r0, c0, racc0, racc1, cacc);
    }
}

__device__ __forceinline__ int triT(int rt) { return rt * 128 - (rt * (rt - 1)) / 2; }

// ---------------- kernel 2: main fused loop (persistent, 148 CTAs) ----------------
__global__ void __launch_bounds__(256, 1) ncl_main_kernel() {
    extern __shared__ char smem[];
    const uint32_t sb = smem_u32(smem);
    const int tid = threadIdx.x;
    const int wid = tid >> 5;
    const int lane = tid & 31;
    const int bx = blockIdx.x;

    const int crow = tid >> 1;
    const int cb = (tid & 1) * 8;
    uint32_t dsto[8];
#pragma unroll
    for (int c = 0; c < 8; c++) dsto[c] = swz(crow, cb + c);

    const int brow_off = (lane & 7) + ((lane & 16) >> 1);
    const int bch = (lane >> 3) & 1;
    const int arow = wid * 16 + (lane & 15);
    const int ach = lane >> 4;
    const int r0 = wid * 16 + (lane >> 2);
    const int c0 = (lane & 3) * 2;

#pragma unroll 1
    for (int phase = 0; phase < 2; phase++) {
        int u, u1;
        if (phase == 0) { u = (bx * UNITS_A) / NSM;  u1 = ((bx + 1) * UNITS_A) / NSM; }
        else            { u = (bx * UNITS_B) / NSM;  u1 = ((bx + 1) * UNITS_B) / NSM; }
        const char* bsrc = (const char*)(phase ? g_h1 : g_h2);

        while (u < u1) {
            int rt, bt;
            if (phase == 0) {
                rt = u >> 7;
                bt = u & 127;
            } else {
                float d = 128.5f * 128.5f - 2.0f * (float)u;
                rt = (int)(128.5f - sqrtf(d));
                if (rt < 0) rt = 0;
                if (rt > 127) rt = 127;
                while (rt < 127 && triT(rt + 1) <= u) rt++;
                while (rt > 0 && triT(rt) > u) rt--;
                bt = rt + (u - triT(rt));
            }
            const int cnt = min(u1 - u, 128 - bt);
            const int nss = (cnt + 1) >> 1;

            // A tile + superstage 0 (up to 2 tiles)
            {
                const char* srcA = (const char*)g_h1 + ((size_t)(rt * 128 + crow) * 128) * 2 + cb * 16;
#pragma unroll
                for (int c = 0; c < 8; c++) cp_async16(sb + SMEM_A + dsto[c], srcA + c * 16);
                cp_commit();
                const int t1n = min(cnt, 2);
                for (int t = 0; t < t1n; t++) {
                    const char* src = bsrc + ((size_t)((bt + t) * 128 + crow) * 128) * 2 + cb * 16;
                    const uint32_t dst = sb + SMEM_S(0) + (uint32_t)((t & 1) * 32768);
#pragma unroll
                    for (int c = 0; c < 8; c++) cp_async16(dst + dsto[c], src + c * 16);
                }
                cp_commit();
            }
            cp_wait<0>();
            __syncthreads();

            uint32_t a[8][4];
#pragma unroll
            for (int ks = 0; ks < 8; ks++)
                ldsm4(a[ks], sb + SMEM_A + swz(arow, ks * 2 + ach));

            float racc0 = 0.f, racc1 = 0.f;
            int pbt0 = -1, pbt1 = -1, psl0 = 0, psl1 = 0;

            for (int ss = 0; ss < nss; ss++) {
                // prefetch next superstage (2 tiles, one group)
                if (ss + 1 < nss) {
                    const int te = min(2 * ss + 4, cnt);
                    const uint32_t dstbase = sb + SMEM_S((ss + 1) & 1);
                    for (int t = 2 * ss + 2; t < te; t++) {
                        const char* src = bsrc + ((size_t)((bt + t) * 128 + crow) * 128) * 2 + cb * 16;
                        const uint32_t dst = dstbase + (uint32_t)((t & 1) * 32768);
#pragma unroll
                        for (int c = 0; c < 8; c++) cp_async16(dst + dsto[c], src + c * 16);
                    }
                    cp_commit();
                }

                // deferred gathers from previous superstage (disjoint slots)
                if (pbt0 >= 0 && tid < 128) {
                    const float* sc = (const float*)(smem + SMEM_C + psl0 * 4096);
                    float s = 0.f;
#pragma unroll
                    for (int w = 0; w < 8; w++) s += sc[w * 128 + tid];
                    atomicAdd(&g_rowsum[pbt0 * 128 + tid], s);
                }
                if (pbt1 >= 0 && tid < 128) {
                    const float* sc = (const float*)(smem + SMEM_C + psl1 * 4096);
                    float s = 0.f;
#pragma unroll
                    for (int w = 0; w < 8; w++) s += sc[w * 128 + tid];
                    atomicAdd(&g_rowsum[pbt1 * 128 + tid], s);
                }
                pbt0 = -1; pbt1 = -1;

                const int tE = min(2 * ss + 2, cnt);
                for (int t = 2 * ss; t < tE; t++) {
                    const int btc = bt + t;
                    const uint32_t sB = sb + SMEM_S(ss & 1) + (uint32_t)((t & 1) * 32768);
                    if (phase == 0) {
                        consume_tile_f<0>(sB, a, brow_off, bch, r0, c0, racc0, racc1, nullptr);
                    } else if (btc == rt) {
                        consume_tile_f<2>(sB, a, brow_off, bch, r0, c0, racc0, racc1, nullptr);
                    } else {
                        float cacc[16][2];
#pragma unroll
                        for (int k = 0; k < 16; k++) { cacc[k][0] = 0.f; cacc[k][1] = 0.f; }
                        consume_tile_f<3>(sB, a, brow_off, bch, r0, c0, racc0, racc1, cacc);
#pragma unroll
                        for (int k = 0; k < 16; k++) {
#pragma unroll
                            for (int q = 0; q < 2; q++) {
                                float vv = cacc[k][q];
                                vv += __shfl_xor_sync(0xffffffffu, vv, 4);
                                vv += __shfl_xor_sync(0xffffffffu, vv, 8);
                                vv += __shfl_xor_sync(0xffffffffu, vv, 16);
                                cacc[k][q] = vv;
                            }
                        }
                        const int slot = t & 3;
                        if (lane < 4) {
                            float2* dst = (float2*)(smem + SMEM_C + slot * 4096 + wid * 512);
#pragma unroll
                            for (int k = 0; k < 16; k++)
                                dst[k * 4 + lane] = make_float2(cacc[k][0], cacc[k][1]);
                        }
                        if (t & 1) { pbt1 = btc; psl1 = slot; }
                        else       { pbt0 = btc; psl0 = slot; }
                    }
                }
                cp_wait<0>();
                __syncthreads();
            }

            // final pending gathers
            if (pbt0 >= 0 && tid < 128) {
                const float* sc = (const float*)(smem + SMEM_C + psl0 * 4096);
                float s = 0.f;
#pragma unroll
                for (int w = 0; w < 8; w++) s += sc[w * 128 + tid];
                atomicAdd(&g_rowsum[pbt0 * 128 + tid], s);
            }
            if (pbt1 >= 0 && tid < 128) {
                const float* sc = (const float*)(smem + SMEM_C + psl1 * 4096);
                float s = 0.f;
#pragma unroll
                for (int w = 0; w < 8; w++) s += sc[w * 128 + tid];
                atomicAdd(&g_rowsum[pbt1 * 128 + tid], s);
            }

            // row partial sums (quad holds disjoint col chunks of same rows)
            racc0 += __shfl_xor_sync(0xffffffffu, racc0, 1);
            racc0 += __shfl_xor_sync(0xffffffffu, racc0, 2);
            racc1 += __shfl_xor_sync(0xffffffffu, racc1, 1);
            racc1 += __shfl_xor_sync(0xffffffffu, racc1, 2);
            if ((lane & 3) == 0) {
                atomicAdd(&g_rowsum[rt * 128 + r0], racc0);
                atomicAdd(&g_rowsum[rt * 128 + r0 + 8], racc1);
            }
            u += cnt;
        }
    }
}

// ---------------- kernel 3: per-row loss + reductions ----------------
__global__ void __launch_bounds__(128) finalize1_kernel() {
    int i = blockIdx.x * 128 + threadIdx.x;
    int wid = threadIdx.x >> 5, lane = threadIdx.x & 31;
    float l = (1.0f - g_pos[i]) * INV_TAU + lg2f(g_rowsum[i]) * LN2F;
#pragma unroll
    for (int o = 16; o; o >>= 1) l += __shfl_xor_sync(0xffffffffu, l, o);
    __shared__ float red[4];
    if (lane == 0) red[wid] = l;
    __syncthreads();
    if (threadIdx.x == 0) g_bsum[blockIdx.x] = red[0] + red[1] + red[2] + red[3];
}

__global__ void finalize2_kernel(float* out) {
    int lane = threadIdx.x;
    float s = g_bsum[lane] + g_bsum[lane + 32] + g_bsum[lane + 64] + g_bsum[lane + 96];
#pragma unroll
    for (int o = 16; o; o >>= 1) s += __shfl_xor_sync(0xffffffffu, s, o);
    if (lane == 0) out[0] = s * (1.0f / (float)N_ROWS);
}

// ---------------- launch ----------------
extern "C" void kernel_launch(void* const* d_in, const int* in_sizes, int n_in,
                              void* d_out, int out_size) {
    const float* z1 = (const float*)d_in[0];
    const float* z2 = (const float*)d_in[1];
    float* out = (float*)d_out;
    (void)in_sizes; (void)n_in; (void)out_size;

    cudaFuncSetAttribute(ncl_main_kernel, cudaFuncAttributeMaxDynamicSharedMemorySize, SMEM_TOTAL);

    norm_kernel<<<N_ROWS / 8, 256>>>(z1, z2);
    ncl_main_kernel<<<NSM, 256, SMEM_TOTAL>>>();
    finalize1_kernel<<<128, 128>>>();
    finalize2_kernel<<<1, 32>>>(out);
}

// round 10
// speedup vs baseline: 2.5779x; 1.1310x over previous
// NodeContrastiveLoss — fused HMMA + streaming LSE, symmetric z1z1 triangle.
// R10: 2 CTAs/SM (grid 296, launch_bounds(256,2), smem 106.5KB/CTA) so one
// CTA's epilogue/barrier bubbles are hidden by the other's MMA stream (2
// warps/SMSP was too thin). Triangle col-flush restructured to per-nb-pair
// shuffle+STS (8 live regs instead of 32) to fit the 128-reg budget.
#include <cuda_runtime.h>
#include <cuda_fp16.h>
#include <cstdint>
#include <cstddef>
#include <cmath>

#define N_ROWS 16384
#define DIM    128
#define NCTA   296
#define UNITS_A 16384        // z1*z2^T: 128 rt x 128 bt
#define UNITS_B 8256         // triangular z1*z1^T units (incl. diagonal)

#define INV_TAU 14.285714285714286f
#define K1F     20.609929155556620f    // log2(e)/tau
#define LN2F    0.6931471805599453f

static __device__ __half g_h1[(size_t)N_ROWS * DIM];
static __device__ __half g_h2[(size_t)N_ROWS * DIM];
static __device__ float  g_pos[N_ROWS];
static __device__ float  g_rowsum[N_ROWS];
static __device__ float  g_bsum[128];

// ---------------- helpers ----------------
__device__ __forceinline__ uint32_t smem_u32(const void* p) {
    uint32_t r;
    asm("{ .reg .u64 t; cvta.to.shared.u64 t, %1; cvt.u32.u64 %0, t; }" : "=r"(r) : "l"(p));
    return r;
}
__device__ __forceinline__ void cp_async16(uint32_t dst, const void* src) {
    asm volatile("cp.async.cg.shared.global [%0], [%1], 16;" :: "r"(dst), "l"(src) : "memory");
}
__device__ __forceinline__ void cp_commit() { asm volatile("cp.async.commit_group;" ::: "memory"); }
template <int N>
__device__ __forceinline__ void cp_wait() { asm volatile("cp.async.wait_group %0;" :: "n"(N) : "memory"); }

__device__ __forceinline__ void ldsm4(uint32_t r[4], uint32_t addr) {
    asm volatile("ldmatrix.sync.aligned.m8n8.x4.shared.b16 {%0,%1,%2,%3}, [%4];"
                 : "=r"(r[0]), "=r"(r[1]), "=r"(r[2]), "=r"(r[3]) : "r"(addr));
}
__device__ __forceinline__ void mma16816(float c[4], const uint32_t a[4], uint32_t b0, uint32_t b1) {
    asm volatile(
        "mma.sync.aligned.m16n8k16.row.col.f32.f16.f16.f32 "
        "{%0,%1,%2,%3}, {%4,%5,%6,%7}, {%8,%9}, {%0,%1,%2,%3};"
        : "+f"(c[0]), "+f"(c[1]), "+f"(c[2]), "+f"(c[3])
        : "r"(a[0]), "r"(a[1]), "r"(a[2]), "r"(a[3]), "r"(b0), "r"(b1));
}
__device__ __forceinline__ float ex2f(float x) { float y; asm("ex2.approx.f32 %0, %1;" : "=f"(y) : "f"(x)); return y; }
__device__ __forceinline__ float lg2f(float x) { float y; asm("lg2.approx.f32 %0, %1;" : "=f"(y) : "f"(x)); return y; }

// f16 tile: 128 rows x 256 B (16 chunks of 16 B). 3-bit XOR swizzle (in-row).
__device__ __forceinline__ uint32_t swz(int row, int c) {
    return (uint32_t)(row * 256 + ((c ^ (row & 7)) << 4));
}

// ---------------- SMEM layout (dynamic, 104 KB/CTA -> 2 CTAs/SM) ----------------
#define SMEM_A  0
#define SMEM_B(s) (32768 + (s) * 32768)   // 2 stages
#define SMEM_C  98304                     // 2 x 4 KB col-sum staging slots
#define SMEM_TOTAL 106496

// ---------------- kernel 1: normalize + f16 + exact pos ----------------
__device__ __forceinline__ float dot4(float4 a, float4 b) {
    return a.x * b.x + a.y * b.y + a.z * b.z + a.w * b.w;
}
__global__ void __launch_bounds__(256) norm_kernel(const float* __restrict__ z1,
                                                   const float* __restrict__ z2) {
    int gw = blockIdx.x * 8 + (threadIdx.x >> 5);
    int lane = threadIdx.x & 31;
    if (threadIdx.x < 8) g_rowsum[blockIdx.x * 8 + threadIdx.x] = 0.f;
    float4 v1 = ((const float4*)(z1 + (size_t)gw * DIM))[lane];
    float4 v2 = ((const float4*)(z2 + (size_t)gw * DIM))[lane];
    float s1 = dot4(v1, v1), s2 = dot4(v2, v2), s12 = dot4(v1, v2);
#pragma unroll
    for (int o = 16; o; o >>= 1) {
        s1  += __shfl_xor_sync(0xffffffffu, s1, o);
        s2  += __shfl_xor_sync(0xffffffffu, s2, o);
        s12 += __shfl_xor_sync(0xffffffffu, s12, o);
    }
    float i1 = rsqrtf(s1), i2 = rsqrtf(s2);
    if (lane == 0) g_pos[gw] = s12 * i1 * i2;
    __half2* d1 = (__half2*)(g_h1 + (size_t)gw * DIM + lane * 4);
    __half2* d2 = (__half2*)(g_h2 + (size_t)gw * DIM + lane * 4);
    d1[0] = __floats2half2_rn(v1.x * i1, v1.y * i1);
    d1[1] = __floats2half2_rn(v1.z * i1, v1.w * i1);
    d2[0] = __floats2half2_rn(v2.x * i2, v2.y * i2);
    d2[1] = __floats2half2_rn(v2.z * i2, v2.w * i2);
}

// ---------------- epilogue for one nb block (f32 accumulators) ----------------
// MODE: 0 row sums; 2 diag tile (mask j==i); 3 triangle tile (row + col sums)
template <int MODE>
__device__ __forceinline__ void epi_f(int nb, const float clo[4], const float chi[4],
                                      int r0, int c0, float& racc0, float& racc1,
                                      float cc[4][2], int ccb) {
    const int nbase = nb * 16;
#pragma unroll
    for (int i = 0; i < 4; i++) {
        const int jl = nbase + c0 + (i & 1);
        const int jh = jl + 8;
        const int rr = r0 + 8 * (i >> 1);
        float el = ex2f(fmaf(clo[i], K1F, -K1F));
        float eh = ex2f(fmaf(chi[i], K1F, -K1F));
        if (MODE == 2) {
            if (jl == rr) el = 0.f;
            if (jh == rr) eh = 0.f;
        }
        if (i >> 1) racc1 += el + eh; else racc0 += el + eh;
        if (MODE == 3) {
            cc[ccb][i & 1]     += el;
            cc[ccb + 1][i & 1] += eh;
        }
    }
}

// ---------------- tile consumer ----------------
// For MODE 3, col partial sums are shuffle-reduced and stored to smem per
// nb-pair (8 live regs), scAddr = SMEM_C slot base.
template <int MODE>
__device__ __forceinline__ void consume_tile_f(
    uint32_t sB, const uint32_t a[8][4], int brow_off, int bch,
    int r0, int c0, float& racc0, float& racc1,
    uint32_t scAddr, int wid, int lane)
{
    const int rx = brow_off & 7;
#pragma unroll
    for (int nbp = 0; nbp < 4; nbp++) {
        const int nb0 = nbp * 2, nb1 = nb0 + 1;
        const uint32_t base0 = sB + (uint32_t)((nb0 * 16 + brow_off) * 256);
        const uint32_t base1 = sB + (uint32_t)((nb1 * 16 + brow_off) * 256);

        uint32_t b0[2][4], b1[2][4];
        ldsm4(b0[0], base0 + (uint32_t)((bch ^ rx) << 4));
        ldsm4(b1[0], base1 + (uint32_t)((bch ^ rx) << 4));

        float c00[4] = {0.f, 0.f, 0.f, 0.f};
        float c01[4] = {0.f, 0.f, 0.f, 0.f};
        float c10[4] = {0.f, 0.f, 0.f, 0.f};
        float c11[4] = {0.f, 0.f, 0.f, 0.f};

#pragma unroll
        for (int ks = 0; ks < 8; ks++) {
            const int cur = ks & 1, nxt = cur ^ 1;
            if (ks < 7) {
                const uint32_t co = (uint32_t)((((ks + 1) * 2 + bch) ^ rx) << 4);
                ldsm4(b0[nxt], base0 + co);
                ldsm4(b1[nxt], base1 + co);
            }
            mma16816(c00, a[ks], b0[cur][0], b0[cur][1]);
            mma16816(c01, a[ks], b0[cur][2], b0[cur][3]);
            mma16816(c10, a[ks], b1[cur][0], b1[cur][1]);
            mma16816(c11, a[ks], b1[cur][2], b1[cur][3]);
        }

        float cc[4][2];
        if (MODE == 3) {
#pragma unroll
            for (int k = 0; k < 4; k++) { cc[k][0] = 0.f; cc[k][1] = 0.f; }
        }
        epi_f<MODE>(nb0, c00, c01, r0, c0, racc0, racc1, cc, 0);
        epi_f<MODE>(nb1, c10, c11, r0, c0, racc0, racc1, cc, 2);

        if (MODE == 3) {
            // reduce over the 8 row-groups (lanes differing in bits 2..4)
#pragma unroll
            for (int k = 0; k < 4; k++) {
#pragma unroll
                for (int q = 0; q < 2; q++) {
                    float vv = cc[k][q];
                    vv += __shfl_xor_sync(0xffffffffu, vv, 4);
                    vv += __shfl_xor_sync(0xffffffffu, vv, 8);
                    vv += __shfl_xor_sync(0xffffffffu, vv, 16);
                    cc[k][q] = vv;
                }
            }
            if (lane < 4) {
                float2* dst = (float2*)0;
                uint32_t base = scAddr + (uint32_t)(wid * 512);
#pragma unroll
                for (int k = 0; k < 4; k++) {
                    const int kk = nbp * 4 + k;
                    uint32_t addr = base + (uint32_t)((kk * 4 + lane) * 8);
                    asm volatile("st.shared.v2.f32 [%0], {%1, %2};"
                                 :: "r"(addr), "f"(cc[k][0]), "f"(cc[k][1]) : "memory");
                }
                (void)dst;
            }
        }
    }
}

__device__ __forceinline__ int triT(int rt) { return rt * 128 - (rt * (rt - 1)) / 2; }

// ---------------- kernel 2: main fused loop (persistent, 296 CTAs, 2/SM) ----------------
__global__ void __launch_bounds__(256, 2) ncl_main_kernel() {
    extern __shared__ char smem[];
    const uint32_t sb = smem_u32(smem);
    const int tid = threadIdx.x;
    const int wid = tid >> 5;
    const int lane = tid & 31;
    const int bx = blockIdx.x;

    const int crow = tid >> 1;
    const int cb = (tid & 1) * 8;
    uint32_t dsto[8];
#pragma unroll
    for (int c = 0; c < 8; c++) dsto[c] = swz(crow, cb + c);

    const int brow_off = (lane & 7) + ((lane & 16) >> 1);
    const int bch = (lane >> 3) & 1;
    const int arow = wid * 16 + (lane & 15);
    const int ach = lane >> 4;
    const int r0 = wid * 16 + (lane >> 2);
    const int c0 = (lane & 3) * 2;

#pragma unroll 1
    for (int phase = 0; phase < 2; phase++) {
        int u, u1;
        if (phase == 0) { u = (bx * UNITS_A) / NCTA;  u1 = ((bx + 1) * UNITS_A) / NCTA; }
        else            { u = (bx * UNITS_B) / NCTA;  u1 = ((bx + 1) * UNITS_B) / NCTA; }
        const char* bsrc = (const char*)(phase ? g_h1 : g_h2);

        while (u < u1) {
            int rt, bt;
            if (phase == 0) {
                rt = u >> 7;
                bt = u & 127;
            } else {
                float d = 128.5f * 128.5f - 2.0f * (float)u;
                rt = (int)(128.5f - sqrtf(d));
                if (rt < 0) rt = 0;
                if (rt > 127) rt = 127;
                while (rt < 127 && triT(rt + 1) <= u) rt++;
                while (rt > 0 && triT(rt) > u) rt--;
                bt = rt + (u - triT(rt));
            }
            const int cnt = min(u1 - u, 128 - bt);

            // one group: A tile + B tile 0
            {
                const char* srcA = (const char*)g_h1 + ((size_t)(rt * 128 + crow) * 128) * 2 + cb * 16;
                const char* srcB = bsrc + ((size_t)(bt * 128 + crow) * 128) * 2 + cb * 16;
#pragma unroll
                for (int c = 0; c < 8; c++) {
                    cp_async16(sb + SMEM_A + dsto[c], srcA + c * 16);
                    cp_async16(sb + SMEM_B(0) + dsto[c], srcB + c * 16);
                }
                cp_commit();
            }

            uint32_t a[8][4];
            float racc0 = 0.f, racc1 = 0.f;
            int pend_bt = -1, pend_slot = 0;

            for (int i = 0; i < cnt; i++) {
                const int btc = bt + i;
                cp_wait<0>();      // tile i (and A on i==0) resident
                __syncthreads();   // all copies visible; all warps done with tile i-1

                if (i == 0) {
#pragma unroll
                    for (int ks = 0; ks < 8; ks++)
                        ldsm4(a[ks], sb + SMEM_A + swz(arow, ks * 2 + ach));
                }
                // prefetch tile i+1 into the other stage (tile i-1 consumers done)
                if (i + 1 < cnt) {
                    const char* src = bsrc + ((size_t)((btc + 1) * 128 + crow) * 128) * 2 + cb * 16;
                    const uint32_t dst = sb + SMEM_B((i + 1) & 1);
#pragma unroll
                    for (int c = 0; c < 8; c++) cp_async16(dst + dsto[c], src + c * 16);
                    cp_commit();
                }
                // deferred gather of previous triangle tile's column sums
                if (pend_bt >= 0 && tid < 128) {
                    const float* sc = (const float*)(smem + SMEM_C + pend_slot * 4096);
                    float s = 0.f;
#pragma unroll
                    for (int w = 0; w < 8; w++) s += sc[w * 128 + tid];
                    atomicAdd(&g_rowsum[pend_bt * 128 + tid], s);
                }
                pend_bt = -1;

                const uint32_t sB = sb + SMEM_B(i & 1);
                if (phase == 0) {
                    consume_tile_f<0>(sB, a, brow_off, bch, r0, c0, racc0, racc1, 0, wid, lane);
                } else if (btc == rt) {
                    consume_tile_f<2>(sB, a, brow_off, bch, r0, c0, racc0, racc1, 0, wid, lane);
                } else {
                    const int slot = i & 1;
                    consume_tile_f<3>(sB, a, brow_off, bch, r0, c0, racc0, racc1,
                                      sb + SMEM_C + (uint32_t)(slot * 4096), wid, lane);
                    pend_bt = btc;
                    pend_slot = slot;
                }
            }

            __syncthreads();   // order last STS before drain
            if (pend_bt >= 0 && tid < 128) {
                const float* sc = (const float*)(smem + SMEM_C + pend_slot * 4096);
                float s = 0.f;
#pragma unroll
                for (int w = 0; w < 8; w++) s += sc[w * 128 + tid];
                atomicAdd(&g_rowsum[pend_bt * 128 + tid], s);
            }

            // row partial sums (quad holds disjoint col chunks of same rows)
            racc0 += __shfl_xor_sync(0xffffffffu, racc0, 1);
            racc0 += __shfl_xor_sync(0xffffffffu, racc0, 2);
            racc1 += __shfl_xor_sync(0xffffffffu, racc1, 1);
            racc1 += __shfl_xor_sync(0xffffffffu, racc1, 2);
            if ((lane & 3) == 0) {
                atomicAdd(&g_rowsum[rt * 128 + r0], racc0);
                atomicAdd(&g_rowsum[rt * 128 + r0 + 8], racc1);
            }
            u += cnt;
        }
    }
}

// ---------------- kernel 3: per-row loss + reductions ----------------
__global__ void __launch_bounds__(128) finalize1_kernel() {
    int i = blockIdx.x * 128 + threadIdx.x;
    int wid = threadIdx.x >> 5, lane = threadIdx.x & 31;
    float l = (1.0f - g_pos[i]) * INV_TAU + lg2f(g_rowsum[i]) * LN2F;
#pragma unroll
    for (int o = 16; o; o >>= 1) l += __shfl_xor_sync(0xffffffffu, l, o);
    __shared__ float red[4];
    if (lane == 0) red[wid] = l;
    __syncthreads();
    if (threadIdx.x == 0) g_bsum[blockIdx.x] = red[0] + red[1] + red[2] + red[3];
}

__global__ void finalize2_kernel(float* out) {
    int lane = threadIdx.x;
    float s = g_bsum[lane] + g_bsum[lane + 32] + g_bsum[lane + 64] + g_bsum[lane + 96];
#pragma unroll
    for (int o = 16; o; o >>= 1) s += __shfl_xor_sync(0xffffffffu, s, o);
    if (lane == 0) out[0] = s * (1.0f / (float)N_ROWS);
}

// ---------------- launch ----------------
extern "C" void kernel_launch(void* const* d_in, const int* in_sizes, int n_in,
                              void* d_out, int out_size) {
    const float* z1 = (const float*)d_in[0];
    const float* z2 = (const float*)d_in[1];
    float* out = (float*)d_out;
    (void)in_sizes; (void)n_in; (void)out_size;

    cudaFuncSetAttribute(ncl_main_kernel, cudaFuncAttributeMaxDynamicSharedMemorySize, SMEM_TOTAL);

    norm_kernel<<<N_ROWS / 8, 256>>>(z1, z2);
    ncl_main_kernel<<<NCTA, 256, SMEM_TOTAL>>>();
    finalize1_kernel<<<128, 128>>>();
    finalize2_kernel<<<1, 32>>>(out);
}

// round 11
// speedup vs baseline: 2.9699x; 1.1521x over previous
// NodeContrastiveLoss — fused fp8(e4m3) mma.sync + streaming LSE, z1z1 triangle.
// R11: HMMA wall (512 MAC/cyc/SM) is the binding constraint at 432us; test the
// legacy fp8 path: m16n8k32.e4m3 = 4096 MAC/instr (2x fp16 if real HW path).
// Fragment/coordinate mapping identical to R4's int8 k32 kernel (proven by its
// structurally-exact diag mask). pos stays exact fp32; keeps 2 CTAs/SM,
// balanced phases, deferred col-flush.
#include <cuda_runtime.h>
#include <cuda_fp8.h>
#include <cstdint>
#include <cstddef>
#include <cmath>

#define N_ROWS 16384
#define DIM    128
#define NCTA   296
#define UNITS_A 16384        // z1*z2^T: 128 rt x 128 bt
#define UNITS_B 8256         // triangular z1*z1^T units (incl. diagonal)

#define INV_TAU 14.285714285714286f
#define K1F     20.609929155556620f    // log2(e)/tau
#define LN2F    0.6931471805599453f

static __device__ uint32_t g_f1[(size_t)N_ROWS * 32];   // e4m3 rows, 4 packed/word
static __device__ uint32_t g_f2[(size_t)N_ROWS * 32];
static __device__ float    g_pos[N_ROWS];
static __device__ float    g_rowsum[N_ROWS];
static __device__ float    g_bsum[128];

// ---------------- helpers ----------------
__device__ __forceinline__ uint32_t smem_u32(const void* p) {
    uint32_t r;
    asm("{ .reg .u64 t; cvta.to.shared.u64 t, %1; cvt.u32.u64 %0, t; }" : "=r"(r) : "l"(p));
    return r;
}
__device__ __forceinline__ void cp_async16(uint32_t dst, const void* src) {
    asm volatile("cp.async.cg.shared.global [%0], [%1], 16;" :: "r"(dst), "l"(src) : "memory");
}
__device__ __forceinline__ void cp_commit() { asm volatile("cp.async.commit_group;" ::: "memory"); }
template <int N>
__device__ __forceinline__ void cp_wait() { asm volatile("cp.async.wait_group %0;" :: "n"(N) : "memory"); }

__device__ __forceinline__ void ldsm4(uint32_t r[4], uint32_t addr) {
    asm volatile("ldmatrix.sync.aligned.m8n8.x4.shared.b16 {%0,%1,%2,%3}, [%4];"
                 : "=r"(r[0]), "=r"(r[1]), "=r"(r[2]), "=r"(r[3]) : "r"(addr));
}
// fp8 e4m3 mma: D,C f32x4; A 4 regs; B 2 regs (k32)
__device__ __forceinline__ void mmafp8(float c[4], const uint32_t a[4], uint32_t b0, uint32_t b1) {
    asm volatile(
        "mma.sync.aligned.m16n8k32.row.col.f32.e4m3.e4m3.f32 "
        "{%0,%1,%2,%3}, {%4,%5,%6,%7}, {%8,%9}, {%0,%1,%2,%3};"
        : "+f"(c[0]), "+f"(c[1]), "+f"(c[2]), "+f"(c[3])
        : "r"(a[0]), "r"(a[1]), "r"(a[2]), "r"(a[3]), "r"(b0), "r"(b1));
}
__device__ __forceinline__ float ex2f(float x) { float y; asm("ex2.approx.f32 %0, %1;" : "=f"(y) : "f"(x)); return y; }
__device__ __forceinline__ float lg2f(float x) { float y; asm("lg2.approx.f32 %0, %1;" : "=f"(y) : "f"(x)); return y; }

// fp8 tile: 128 rows x 128 B (8 chunks of 16 B), 3-bit XOR swizzle (R4-proven).
__device__ __forceinline__ uint32_t swz8(int row, int c) {
    return (uint32_t)(row * 128 + (((c ^ row) & 7) << 4));
}

// ---------------- SMEM layout (dynamic, 56 KB/CTA) ----------------
#define SMEM_A  0
#define SMEM_B(s) (16384 + (s) * 16384)   // 2 stages x 16 KB
#define SMEM_C  49152                     // 2 x 4 KB col-sum staging slots
#define SMEM_TOTAL 57344

// ---------------- kernel 1: normalize + e4m3 + exact pos ----------------
__device__ __forceinline__ float dot4(float4 a, float4 b) {
    return a.x * b.x + a.y * b.y + a.z * b.z + a.w * b.w;
}
__device__ __forceinline__ uint32_t pack_fp8(float4 v, float s) {
    __nv_fp8x2_storage_t lo = __nv_cvt_float2_to_fp8x2(make_float2(v.x * s, v.y * s),
                                                       __NV_SATFINITE, __NV_E4M3);
    __nv_fp8x2_storage_t hi = __nv_cvt_float2_to_fp8x2(make_float2(v.z * s, v.w * s),
                                                       __NV_SATFINITE, __NV_E4M3);
    return (uint32_t)lo | ((uint32_t)hi << 16);
}
__global__ void __launch_bounds__(256) norm_kernel(const float* __restrict__ z1,
                                                   const float* __restrict__ z2) {
    int gw = blockIdx.x * 8 + (threadIdx.x >> 5);
    int lane = threadIdx.x & 31;
    if (threadIdx.x < 8) g_rowsum[blockIdx.x * 8 + threadIdx.x] = 0.f;
    float4 v1 = ((const float4*)(z1 + (size_t)gw * DIM))[lane];
    float4 v2 = ((const float4*)(z2 + (size_t)gw * DIM))[lane];
    float s1 = dot4(v1, v1), s2 = dot4(v2, v2), s12 = dot4(v1, v2);
#pragma unroll
    for (int o = 16; o; o >>= 1) {
        s1  += __shfl_xor_sync(0xffffffffu, s1, o);
        s2  += __shfl_xor_sync(0xffffffffu, s2, o);
        s12 += __shfl_xor_sync(0xffffffffu, s12, o);
    }
    float i1 = rsqrtf(s1), i2 = rsqrtf(s2);
    if (lane == 0) g_pos[gw] = s12 * i1 * i2;   // exact fp32 positive similarity
    g_f1[(size_t)gw * 32 + lane] = pack_fp8(v1, i1);
    g_f2[(size_t)gw * 32 + lane] = pack_fp8(v2, i2);
}

// ---------------- epilogue for one nb block ----------------
// MODE: 0 row sums; 2 diag tile (mask j==i); 3 triangle tile (row + col sums)
template <int MODE>
__device__ __forceinline__ void epi_f(int nb, const float clo[4], const float chi[4],
                                      int r0, int c0, float& racc0, float& racc1,
                                      float cc[4][2], int ccb) {
    const int nbase = nb * 16;
#pragma unroll
    for (int i = 0; i < 4; i++) {
        const int jl = nbase + c0 + (i & 1);
        const int jh = jl + 8;
        const int rr = r0 + 8 * (i >> 1);
        float el = ex2f(fmaf(clo[i], K1F, -K1F));
        float eh = ex2f(fmaf(chi[i], K1F, -K1F));
        if (MODE == 2) {
            if (jl == rr) el = 0.f;
            if (jh == rr) eh = 0.f;
        }
        if (i >> 1) racc1 += el + eh; else racc0 += el + eh;
        if (MODE == 3) {
            cc[ccb][i & 1]     += el;
            cc[ccb + 1][i & 1] += eh;
        }
    }
}

// ---------------- tile consumer (fp8, 4 K-steps; R4-proven mapping) ----------------
template <int MODE>
__device__ __forceinline__ void consume_tile_f8(
    uint32_t sB, const uint32_t a[4][4], int brow, int bsel,
    int r0, int c0, float& racc0, float& racc1,
    uint32_t scAddr, int wid, int lane)
{
    const int rx = brow & 7;
#pragma unroll
    for (int nbp = 0; nbp < 4; nbp++) {
        const int nb0 = nbp * 2, nb1 = nb0 + 1;
        const uint32_t base0 = sB + (uint32_t)((nb0 * 16 + brow) * 128);
        const uint32_t base1 = sB + (uint32_t)((nb1 * 16 + brow) * 128);

        uint32_t b0[2][4], b1[2][4];
        ldsm4(b0[0], base0 + (uint32_t)((bsel ^ rx) << 4));
        ldsm4(b1[0], base1 + (uint32_t)((bsel ^ rx) << 4));

        float c00[4] = {0.f, 0.f, 0.f, 0.f};
        float c01[4] = {0.f, 0.f, 0.f, 0.f};
        float c10[4] = {0.f, 0.f, 0.f, 0.f};
        float c11[4] = {0.f, 0.f, 0.f, 0.f};

#pragma unroll
        for (int ks = 0; ks < 4; ks++) {
            const int cur = ks & 1, nxt = cur ^ 1;
            if (ks < 3) {
                const uint32_t co = (uint32_t)(((2 * (ks + 1) + bsel) ^ rx) << 4);
                ldsm4(b0[nxt], base0 + co);
                ldsm4(b1[nxt], base1 + co);
            }
            // n-lo block uses regs {0,2} (k-lo,k-hi); n-hi uses {1,3}
            mmafp8(c00, a[ks], b0[cur][0], b0[cur][2]);
            mmafp8(c01, a[ks], b0[cur][1], b0[cur][3]);
            mmafp8(c10, a[ks], b1[cur][0], b1[cur][2]);
            mmafp8(c11, a[ks], b1[cur][1], b1[cur][3]);
        }

        float cc[4][2];
        if (MODE == 3) {
#pragma unroll
            for (int k = 0; k < 4; k++) { cc[k][0] = 0.f; cc[k][1] = 0.f; }
        }
        epi_f<MODE>(nb0, c00, c01, r0, c0, racc0, racc1, cc, 0);
        epi_f<MODE>(nb1, c10, c11, r0, c0, racc0, racc1, cc, 2);

        if (MODE == 3) {
#pragma unroll
            for (int k = 0; k < 4; k++) {
#pragma unroll
                for (int q = 0; q < 2; q++) {
                    float vv = cc[k][q];
                    vv += __shfl_xor_sync(0xffffffffu, vv, 4);
                    vv += __shfl_xor_sync(0xffffffffu, vv, 8);
                    vv += __shfl_xor_sync(0xffffffffu, vv, 16);
                    cc[k][q] = vv;
                }
            }
            if (lane < 4) {
                uint32_t base = scAddr + (uint32_t)(wid * 512);
#pragma unroll
                for (int k = 0; k < 4; k++) {
                    const int kk = nbp * 4 + k;
                    uint32_t addr = base + (uint32_t)((kk * 4 + lane) * 8);
                    asm volatile("st.shared.v2.f32 [%0], {%1, %2};"
                                 :: "r"(addr), "f"(cc[k][0]), "f"(cc[k][1]) : "memory");
                }
            }
        }
    }
}

__device__ __forceinline__ int triT(int rt) { return rt * 128 - (rt * (rt - 1)) / 2; }

// ---------------- kernel 2: main fused loop (persistent, 296 CTAs, 2/SM) ----------------
__global__ void __launch_bounds__(256, 2) ncl_main_kernel() {
    extern __shared__ char smem[];
    const uint32_t sb = smem_u32(smem);
    const int tid = threadIdx.x;
    const int wid = tid >> 5;
    const int lane = tid & 31;
    const int bx = blockIdx.x;

    // copy slots: row = tid/2, 4 chunks of 16B starting at (tid&1)*4
    const int crow = tid >> 1;
    const int cc0 = (tid & 1) * 4;
    uint32_t dsto[4];
#pragma unroll
    for (int c = 0; c < 4; c++) dsto[c] = swz8(crow, cc0 + c);

    const int brow = lane & 15;          // ldsm row within 16-row block
    const int bsel = lane >> 4;          // k-chunk select
    const int arow = wid * 16 + (lane & 15);
    const int r0 = wid * 16 + (lane >> 2);
    const int c0 = (lane & 3) * 2;

#pragma unroll 1
    for (int phase = 0; phase < 2; phase++) {
        int u, u1;
        if (phase == 0) { u = (bx * UNITS_A) / NCTA;  u1 = ((bx + 1) * UNITS_A) / NCTA; }
        else            { u = (bx * UNITS_B) / NCTA;  u1 = ((bx + 1) * UNITS_B) / NCTA; }
        const char* bsrc = (const char*)(phase ? g_f1 : g_f2);

        while (u < u1) {
            int rt, bt;
            if (phase == 0) {
                rt = u >> 7;
                bt = u & 127;
            } else {
                float d = 128.5f * 128.5f - 2.0f * (float)u;
                rt = (int)(128.5f - sqrtf(d));
                if (rt < 0) rt = 0;
                if (rt > 127) rt = 127;
                while (rt < 127 && triT(rt + 1) <= u) rt++;
                while (rt > 0 && triT(rt) > u) rt--;
                bt = rt + (u - triT(rt));
            }
            const int cnt = min(u1 - u, 128 - bt);

            // one group: A tile + B tile 0
            {
                const char* srcA = (const char*)g_f1 + ((size_t)(rt * 128 + crow) * 128) + cc0 * 16;
                const char* srcB = bsrc + ((size_t)(bt * 128 + crow) * 128) + cc0 * 16;
#pragma unroll
                for (int c = 0; c < 4; c++) {
                    cp_async16(sb + SMEM_A + dsto[c], srcA + c * 16);
                    cp_async16(sb + SMEM_B(0) + dsto[c], srcB + c * 16);
                }
                cp_commit();
            }

            uint32_t a[4][4];
            float racc0 = 0.f, racc1 = 0.f;
            int pend_bt = -1, pend_slot = 0;

            for (int i = 0; i < cnt; i++) {
                const int btc = bt + i;
                cp_wait<0>();      // tile i (and A on i==0) resident
                __syncthreads();   // all copies visible; all warps done with tile i-1

                if (i == 0) {
#pragma unroll
                    for (int ks = 0; ks < 4; ks++)
                        ldsm4(a[ks], sb + SMEM_A + swz8(arow, 2 * ks + bsel));
                }
                // prefetch tile i+1 into the other stage
                if (i + 1 < cnt) {
                    const char* src = bsrc + ((size_t)((btc + 1) * 128 + crow) * 128) + cc0 * 16;
                    const uint32_t dst = sb + SMEM_B((i + 1) & 1);
#pragma unroll
                    for (int c = 0; c < 4; c++) cp_async16(dst + dsto[c], src + c * 16);
                    cp_commit();
                }
                // deferred gather of previous triangle tile's column sums
                if (pend_bt >= 0 && tid < 128) {
                    const float* sc = (const float*)(smem + SMEM_C + pend_slot * 4096);
                    float s = 0.f;
#pragma unroll
                    for (int w = 0; w < 8; w++) s += sc[w * 128 + tid];
                    atomicAdd(&g_rowsum[pend_bt * 128 + tid], s);
                }
                pend_bt = -1;

                const uint32_t sB = sb + SMEM_B(i & 1);
                if (phase == 0) {
                    consume_tile_f8<0>(sB, a, brow, bsel, r0, c0, racc0, racc1, 0, wid, lane);
                } else if (btc == rt) {
                    consume_tile_f8<2>(sB, a, brow, bsel, r0, c0, racc0, racc1, 0, wid, lane);
                } else {
                    const int slot = i & 1;
                    consume_tile_f8<3>(sB, a, brow, bsel, r0, c0, racc0, racc1,
                                       sb + SMEM_C + (uint32_t)(slot * 4096), wid, lane);
                    pend_bt = btc;
                    pend_slot = slot;
                }
            }

            __syncthreads();   // order last STS before drain
            if (pend_bt >= 0 && tid < 128) {
                const float* sc = (const float*)(smem + SMEM_C + pend_slot * 4096);
                float s = 0.f;
#pragma unroll
                for (int w = 0; w < 8; w++) s += sc[w * 128 + tid];
                atomicAdd(&g_rowsum[pend_bt * 128 + tid], s);
            }

            // row partial sums (quad holds disjoint col chunks of same rows)
            racc0 += __shfl_xor_sync(0xffffffffu, racc0, 1);
            racc0 += __shfl_xor_sync(0xffffffffu, racc0, 2);
            racc1 += __shfl_xor_sync(0xffffffffu, racc1, 1);
            racc1 += __shfl_xor_sync(0xffffffffu, racc1, 2);
            if ((lane & 3) == 0) {
                atomicAdd(&g_rowsum[rt * 128 + r0], racc0);
                atomicAdd(&g_rowsum[rt * 128 + r0 + 8], racc1);
            }
            u += cnt;
        }
    }
}

// ---------------- kernel 3: per-row loss + reductions ----------------
__global__ void __launch_bounds__(128) finalize1_kernel() {
    int i = blockIdx.x * 128 + threadIdx.x;
    int wid = threadIdx.x >> 5, lane = threadIdx.x & 31;
    float l = (1.0f - g_pos[i]) * INV_TAU + lg2f(g_rowsum[i]) * LN2F;
#pragma unroll
    for (int o = 16; o; o >>= 1) l += __shfl_xor_sync(0xffffffffu, l, o);
    __shared__ float red[4];
    if (lane == 0) red[wid] = l;
    __syncthreads();
    if (threadIdx.x == 0) g_bsum[blockIdx.x] = red[0] + red[1] + red[2] + red[3];
}

__global__ void finalize2_kernel(float* out) {
    int lane = threadIdx.x;
    float s = g_bsum[lane] + g_bsum[lane + 32] + g_bsum[lane + 64] + g_bsum[lane + 96];
#pragma unroll
    for (int o = 16; o; o >>= 1) s += __shfl_xor_sync(0xffffffffu, s, o);
    if (lane == 0) out[0] = s * (1.0f / (float)N_ROWS);
}

// ---------------- launch ----------------
extern "C" void kernel_launch(void* const* d_in, const int* in_sizes, int n_in,
                              void* d_out, int out_size) {
    const float* z1 = (const float*)d_in[0];
    const float* z2 = (const float*)d_in[1];
    float* out = (float*)d_out;
    (void)in_sizes; (void)n_in; (void)out_size;

    cudaFuncSetAttribute(ncl_main_kernel, cudaFuncAttributeMaxDynamicSharedMemorySize, SMEM_TOTAL);

    norm_kernel<<<N_ROWS / 8, 256>>>(z1, z2);
    ncl_main_kernel<<<NCTA, 256, SMEM_TOTAL>>>();
    finalize1_kernel<<<128, 128>>>();
    finalize2_kernel<<<1, 32>>>(out);
}